// round 6
// baseline (speedup 1.0000x reference)
#include <cuda_runtime.h>
#include <cstdint>

#define B_   16
#define N_   128
#define M_   1024
#define DN_  512
#define DE_  256
#define WN_  128
#define WE_  128
#define P_   512

// ------------------------- scratch (device globals) -------------------------
__device__ float d_XWc  [B_*N_*256];     // [X@Wn | X@Wn2] (row-masked)
__device__ float d_nemb [B_*N_*256];     // [h | agg] per node
__device__ float d_nodeY[B_*N_*768];     // nemb @ W1c[0:256]
__device__ float d_EgWe [B_*M_*WE_];     // Eg@We (gather fused into GEMM)
__device__ float d_g    [B_*M_*WE_];     // relu(L@EgWe)*emask
__device__ float d_pf   [B_*P_*256];     // [Pm | Q] per pair
__device__ float d_hidB [B_*P_*768];     // pf @ W1c[256:512] + b1c (no relu)
__device__ float d_Wc   [DN_*256];       // [Wn | Wn2]
__device__ float d_W1c  [512*768];       // concat(lr_W1, scr_W1, mr_W1) along cols
__device__ float d_b1c  [768];
__device__ int   d_ord  [B_*M_];         // CSR edge order by src
__device__ int   d_st   [B_*(N_+1)];     // CSR bucket starts

__device__ __forceinline__ uint32_t f2tf32(float x) {
    uint32_t r;
    asm("cvt.rna.tf32.f32 %0, %1;" : "=r"(r) : "f"(x));
    return r;
}

// ============ TF32 tensor-core GEMM tile (128x128, 8 warps), device fn ======
// MODE 0: A is dense [M,K].  MODE 1: A row r -> EF[b, src[m], dst[m]] with
// emask (b=r/M_, m=r%M_).  MODE 2: A row r -> EF[b, p0, p1] (b=r/P_, p=r%P_).
// C tile (bx,by) of C = A @ B (+bias, relu, row-mask). K%32==0.
template<int MODE>
__device__ __forceinline__
void gemm_tile(const float* __restrict__ A, const float* __restrict__ Bw,
               float* __restrict__ C, int K, int N, int ldc,
               const float* __restrict__ bias, int relu,
               const int* __restrict__ rowcnt, int rpb,
               int bx, int by,
               const float* __restrict__ EF, const int* __restrict__ eidx,
               const int* __restrict__ nedg, const int* __restrict__ pairs)
{
    __shared__ uint32_t As[32][136];   // [k][m], pad 8 -> conflict-free frags
    __shared__ uint32_t Bs[32][136];   // [k][n]
    const int tid  = threadIdx.x;
    const int m0 = by * 128, n0 = bx * 128;
    const int lane = tid & 31, warp = tid >> 5;
    const int wm = (warp & 1) * 64, wn = (warp >> 1) * 32;
    const int g  = lane >> 2, t4 = lane & 3;

    const int am = tid >> 1;          // A loader: m row 0..127
    const int ak = (tid & 1) * 4;     //           k quad within 8
    const int bk = tid >> 5;          // B loader: k row 0..7
    const int bn = (tid & 31) * 4;    //           n quad

    // Resolve this thread's A row pointer (gather fused for MODE 1/2)
    const float* Arow;
    bool aon = true;
    {
        int r = m0 + am;
        if (MODE == 0) {
            Arow = A + (size_t)r * K;
        } else if (MODE == 1) {
            int b = r / M_, m = r % M_;
            int s  = eidx[(b * 2 + 0) * M_ + m];
            int dd = eidx[(b * 2 + 1) * M_ + m];
            aon = m < nedg[b];
            Arow = EF + (((size_t)b * N_ + s) * N_ + dd) * DE_;
        } else {
            int b = r / P_, p = r % P_;
            int p0 = pairs[((size_t)b * P_ + p) * 2 + 0];
            int p1 = pairs[((size_t)b * P_ + p) * 2 + 1];
            Arow = EF + (((size_t)b * N_ + p0) * N_ + p1) * DE_;
        }
    }

    float acc[4][4][4];
#pragma unroll
    for (int a = 0; a < 4; a++)
#pragma unroll
        for (int b = 0; b < 4; b++)
#pragma unroll
            for (int c = 0; c < 4; c++) acc[a][b][c] = 0.0f;

    const float4 z4 = make_float4(0.f, 0.f, 0.f, 0.f);
    for (int k0 = 0; k0 < K; k0 += 32) {
#pragma unroll
        for (int ks = 0; ks < 32; ks += 8) {
            float4 v = aon ? *(const float4*)(Arow + k0 + ks + ak) : z4;
            As[ks + ak + 0][am] = f2tf32(v.x);
            As[ks + ak + 1][am] = f2tf32(v.y);
            As[ks + ak + 2][am] = f2tf32(v.z);
            As[ks + ak + 3][am] = f2tf32(v.w);
        }
#pragma unroll
        for (int ks = 0; ks < 32; ks += 8) {
            float4 v = *(const float4*)(Bw + (size_t)(k0 + ks + bk) * N + n0 + bn);
            uint32_t* p = &Bs[ks + bk][bn];
            p[0] = f2tf32(v.x); p[1] = f2tf32(v.y);
            p[2] = f2tf32(v.z); p[3] = f2tf32(v.w);
        }
        __syncthreads();
#pragma unroll
        for (int kk = 0; kk < 32; kk += 8) {
            uint32_t aF[4][4], bF[4][2];
#pragma unroll
            for (int mt = 0; mt < 4; mt++) {
                int mb = wm + mt * 16 + g;
                aF[mt][0] = As[kk + t4    ][mb];
                aF[mt][1] = As[kk + t4    ][mb + 8];
                aF[mt][2] = As[kk + t4 + 4][mb];
                aF[mt][3] = As[kk + t4 + 4][mb + 8];
            }
#pragma unroll
            for (int nt = 0; nt < 4; nt++) {
                int nb = wn + nt * 8 + g;
                bF[nt][0] = Bs[kk + t4    ][nb];
                bF[nt][1] = Bs[kk + t4 + 4][nb];
            }
#pragma unroll
            for (int mt = 0; mt < 4; mt++)
#pragma unroll
                for (int nt = 0; nt < 4; nt++)
                    asm volatile(
                        "mma.sync.aligned.m16n8k8.row.col.f32.tf32.tf32.f32 "
                        "{%0,%1,%2,%3}, {%4,%5,%6,%7}, {%8,%9}, {%0,%1,%2,%3};"
                        : "+f"(acc[mt][nt][0]), "+f"(acc[mt][nt][1]),
                          "+f"(acc[mt][nt][2]), "+f"(acc[mt][nt][3])
                        : "r"(aF[mt][0]), "r"(aF[mt][1]), "r"(aF[mt][2]), "r"(aF[mt][3]),
                          "r"(bF[nt][0]), "r"(bF[nt][1]));
        }
        __syncthreads();
    }

#pragma unroll
    for (int mt = 0; mt < 4; mt++) {
        int row0 = m0 + wm + mt * 16 + g;
        int row1 = row0 + 8;
        float mask0 = 1.0f, mask1 = 1.0f;
        if (rowcnt) {
            if (row0 % rpb >= rowcnt[row0 / rpb]) mask0 = 0.0f;
            if (row1 % rpb >= rowcnt[row1 / rpb]) mask1 = 0.0f;
        }
        float* c0p = C + (size_t)row0 * ldc;
        float* c1p = C + (size_t)row1 * ldc;
#pragma unroll
        for (int nt = 0; nt < 4; nt++) {
            int col = n0 + wn + nt * 8 + 2 * t4;
            float v0 = acc[mt][nt][0], v1 = acc[mt][nt][1];
            float v2 = acc[mt][nt][2], v3 = acc[mt][nt][3];
            if (bias) {
                float b0 = bias[col], b1 = bias[col + 1];
                v0 += b0; v1 += b1; v2 += b0; v3 += b1;
            }
            if (relu) {
                v0 = fmaxf(v0, 0.f); v1 = fmaxf(v1, 0.f);
                v2 = fmaxf(v2, 0.f); v3 = fmaxf(v3, 0.f);
            }
            float2 w0 = make_float2(v0 * mask0, v1 * mask0);
            float2 w1 = make_float2(v2 * mask1, v3 * mask1);
            *(float2*)(c0p + col) = w0;
            *(float2*)(c1p + col) = w1;
        }
    }
}

// ---- batch A: XWc (32, K=512) | EgWe gather-fused (128) | Q gather-fused (64)
__global__ __launch_bounds__(256)
void gemm_batchA(const float* __restrict__ NF, const float* __restrict__ EF,
                 const float* __restrict__ We, const float* __restrict__ We2,
                 const int* __restrict__ EIDX, const int* __restrict__ PAIRS,
                 const int* __restrict__ NOBJ, const int* __restrict__ NEDG)
{
    int bid = blockIdx.x;
    if (bid < 32) {
        // XWc = mask(NF @ [Wn|Wn2])          [2048 x 256 x 512]
        gemm_tile<0>(NF, d_Wc, d_XWc, DN_, 256, 256, nullptr, 0, NOBJ, N_,
                     bid & 1, bid >> 1, nullptr, nullptr, nullptr, nullptr);
    } else if (bid < 160) {
        // EgWe = (gather EF by edge) @ We    [16384 x 128 x 256]
        gemm_tile<1>(nullptr, We, d_EgWe, DE_, WE_, WE_, nullptr, 0, nullptr, 0,
                     0, bid - 32, EF, EIDX, NEDG, nullptr);
    } else {
        // Q = relu((gather EF by pair) @ We2) -> pf cols [128:256), ldc=256
        gemm_tile<2>(nullptr, We2, d_pf + 128, DE_, WE_, 256, nullptr, 1, nullptr, 0,
                     0, bid - 160, EF, nullptr, nullptr, PAIRS);
    }
}

// ---- batch B: hidB (384 tiles) | nodeY (96 tiles) --------------------------
__global__ __launch_bounds__(256)
void gemm_batchB()
{
    int bid = blockIdx.x;
    if (bid < 384) {
        // hidB = pf @ W1c[256:512,:] + b1c   [8192 x 768 x 256]
        gemm_tile<0>(d_pf, d_W1c + 256 * 768, d_hidB, 256, 768, 768,
                     d_b1c, 0, nullptr, 0, bid % 6, bid / 6,
                     nullptr, nullptr, nullptr, nullptr);
    } else {
        // nodeY = nemb @ W1c[0:256,:]        [2048 x 768 x 256]
        int t = bid - 384;
        gemm_tile<0>(d_nemb, d_W1c, d_nodeY, 256, 768, 768,
                     nullptr, 0, nullptr, 0, t % 6, t / 6,
                     nullptr, nullptr, nullptr, nullptr);
    }
}

// ------ stage 3 merged: h (2048) | g (16384) | pm (8192), all 128 threads ---
__global__ __launch_bounds__(128)
void stage3(const float* __restrict__ ADJ, const float* __restrict__ LADJ,
            const int* __restrict__ PAIRS, const int* __restrict__ NOBJ,
            const int* __restrict__ NEDG)
{
    __shared__ float sf[M_];       // g: s_val ; h: arow (first 128)
    __shared__ int   si[M_];       // g: s_idx
    __shared__ int   sc[129];      // g: s_cnt
    int bid = blockIdx.x;
    int w = threadIdx.x;           // 128

    if (bid < B_ * N_) {
        // ---- h: relu(XW_i + sum_j adj_ij*XW_j)*mask -> nemb cols [0:128) ----
        int b = bid / N_, i = bid % N_;
        sf[w] = ADJ[((size_t)b * N_ + i) * N_ + w];
        __syncthreads();
        const float* XWb = d_XWc + (size_t)b * N_ * 256;   // cols [0:128)
        float acc = XWb[i * 256 + w];
        for (int j = 0; j < N_; j++) {
            float a = sf[j];
            if (a != 0.0f) acc += a * XWb[j * 256 + w];
        }
        d_nemb[((size_t)b * N_ + i) * 256 + w] =
            (i < NOBJ[b]) ? fmaxf(acc, 0.0f) : 0.0f;
    } else if (bid < B_ * N_ + B_ * M_) {
        // ---- g = relu(EgWe_m + sum_k L_mk*EgWe_k)*emask (sparse L) ----------
        int t = bid - B_ * N_;
        int b = t / M_, m = t % M_;
        const float* Lrow = LADJ + ((size_t)b * M_ + m) * M_;
        float v[8];
        int cnt = 0, base = w * 8;
#pragma unroll
        for (int q = 0; q < 8; q++) {
            v[q] = Lrow[base + q];
            if (v[q] != 0.0f) cnt++;
        }
        sc[w + 1] = cnt;
        if (w == 0) sc[0] = 0;
        __syncthreads();
        if (w == 0)
            for (int q = 1; q <= 128; q++) sc[q] += sc[q - 1];
        __syncthreads();
        int pos = sc[w];
#pragma unroll
        for (int q = 0; q < 8; q++)
            if (v[q] != 0.0f) { si[pos] = base + q; sf[pos] = v[q]; pos++; }
        __syncthreads();
        int total = sc[128];
        const float* Eb = d_EgWe + (size_t)b * M_ * WE_;
        float acc = Eb[m * WE_ + w];          // identity (EgWe rows emasked)
        for (int p = 0; p < total; p++)
            acc += sf[p] * Eb[si[p] * WE_ + w];
        d_g[((size_t)b * M_ + m) * WE_ + w] =
            (m < NEDG[b]) ? fmaxf(acc, 0.0f) : 0.0f;
    } else {
        // ---- Pm = relu(XW2[p0]+XW2[p1]) -> pf cols [0:128) ------------------
        int t = bid - B_ * N_ - B_ * M_;
        int b = t / P_, p = t % P_;
        int p0 = PAIRS[((size_t)b * P_ + p) * 2 + 0];
        int p1 = PAIRS[((size_t)b * P_ + p) * 2 + 1];
        const float* xb = d_XWc + (size_t)b * N_ * 256 + 128;   // cols [128:256)
        d_pf[((size_t)b * P_ + p) * 256 + w] =
            fmaxf(xb[(size_t)p0 * 256 + w] + xb[(size_t)p1 * 256 + w], 0.0f);
    }
}

// ---------------- CSR build: bucket edges by src, stable in m ---------------
__global__ __launch_bounds__(1024)
void csr_kernel(const int* __restrict__ eidx,
                int* __restrict__ order, int* __restrict__ start)
{
    int b = blockIdx.x, m = threadIdx.x;    // 1024 threads
    int warp = m >> 5, lane = m & 31;
    __shared__ int ssrc[M_];
    __shared__ int wcnt[32][N_];            // per-warp histogram
    __shared__ int cnt[N_ + 1];
    ssrc[m] = eidx[(b * 2 + 0) * M_ + m];
    for (int i = m; i < 32 * N_; i += 1024) (&wcnt[0][0])[i] = 0;
    __syncthreads();
    int s = ssrc[m];
    unsigned mk = __match_any_sync(0xffffffffu, s);
    int rank_w = __popc(mk & ((1u << lane) - 1));
    if (lane == (__ffs(mk) - 1)) wcnt[warp][s] = __popc(mk);
    __syncthreads();
    int rank = rank_w;
    for (int ww = 0; ww < warp; ww++) rank += wcnt[ww][s];
    if (m < N_) {
        int t = 0;
        for (int ww = 0; ww < 32; ww++) t += wcnt[ww][m];
        cnt[m + 1] = t;
    }
    if (m == 0) cnt[0] = 0;
    __syncthreads();
    if (m == 0)
        for (int i = 1; i <= N_; i++) cnt[i] += cnt[i - 1];
    __syncthreads();
    order[b * M_ + cnt[s] + rank] = m;
    if (m < N_ + 1) start[b * (N_ + 1) + m] = cnt[m];
}

// -------- agg[b,n] = sum_{m in bucket n, ascending m} g[b,m] * nmask --------
__global__ void agg2_kernel(const int* __restrict__ nobj)
{
    int b = blockIdx.x / N_, n = blockIdx.x % N_;
    int w = threadIdx.x;                    // 128
    int s0 = d_st[b * (N_ + 1) + n], s1 = d_st[b * (N_ + 1) + n + 1];
    const float* gb = d_g + (size_t)b * M_ * WE_;
    const int* ob = d_ord + b * M_;
    float acc = 0.0f;
    for (int i = s0; i < s1; i++)
        acc += gb[(size_t)ob[i] * WE_ + w];
    d_nemb[((size_t)b * N_ + n) * 256 + 128 + w] = (n < nobj[b]) ? acc : 0.0f;
}

// --------------- concat weights: Wc=[Wn|Wn2], W1c, b1c ----------------------
__global__ void catw1(const float* __restrict__ Wn, const float* __restrict__ Wn2,
                      const float* __restrict__ lrW1, const float* __restrict__ scrW1,
                      const float* __restrict__ mrW1, const float* __restrict__ lrb1,
                      const float* __restrict__ scrb1, const float* __restrict__ mrb1)
{
    int k = blockIdx.x, c = threadIdx.x;    // 512 blocks, 256 threads
    d_W1c[k * 768 + c]       = lrW1 [k * 256 + c];
    d_W1c[k * 768 + 256 + c] = scrW1[k * 256 + c];
    d_W1c[k * 768 + 512 + c] = mrW1 [k * 256 + c];
    d_Wc[k * 256 + c] = (c < 128) ? Wn[k * 128 + c] : Wn2[k * 128 + (c - 128)];
    if (k == 0) {
        d_b1c[c]       = lrb1[c];
        d_b1c[256 + c] = scrb1[c];
        d_b1c[512 + c] = mrb1[c];
    }
}

// ------ layer-2 heads: hid = relu(hidB + nodeY[p0] + nodeY[p1]) fused -------
__global__ void head2_kernel(const int* __restrict__ pairs,
                             const float* __restrict__ lrW2, const float* __restrict__ lrb2,
                             const float* __restrict__ crW2, const float* __restrict__ crb2,
                             const float* __restrict__ mrW2, const float* __restrict__ mrb2,
                             float* __restrict__ out)
{
    __shared__ float sh[8 * 768];
    __shared__ int sp[16];
    int tid = threadIdx.x;                  // 256
    int blk = blockIdx.x;                   // 8 pairs per block
    if (tid < 16) sp[tid] = pairs[(size_t)blk * 16 + tid];
    __syncthreads();
    int b = (blk * 8) / P_;                 // all 8 pairs share batch (P_%8==0)
    const float* nYb = d_nodeY + (size_t)b * N_ * 768;
    for (int i = tid; i < 8 * 768; i += 256) {
        int lp = i / 768, col = i - lp * 768;
        int gg = blk * 8 + lp;
        float v = d_hidB[(size_t)gg * 768 + col]
                + nYb[(size_t)sp[lp * 2 + 0] * 768 + col]
                + nYb[(size_t)sp[lp * 2 + 1] * 768 + col];
        sh[i] = fmaxf(v, 0.0f);
    }
    __syncthreads();
    int lp = tid / 32, j = tid % 32;
    int pr = blk * 8 + lp;
    const float* W2; float bias; int nout, oj; const float* hr; size_t obase;
    if (j < 9)       { W2 = lrW2; oj = j;      bias = lrb2[oj]; nout = 9;  hr = sh + lp * 768;       obase = 0; }
    else if (j < 15) { W2 = crW2; oj = j - 9;  bias = crb2[oj]; nout = 6;  hr = sh + lp * 768 + 256; obase = (size_t)B_ * P_ * 9; }
    else             { W2 = mrW2; oj = j - 15; bias = mrb2[oj]; nout = 17; hr = sh + lp * 768 + 512; obase = (size_t)B_ * P_ * 15; }
    float acc = bias;
#pragma unroll 8
    for (int k = 0; k < 256; k++)
        acc += hr[k] * W2[k * nout + oj];
    out[obase + (size_t)pr * nout + oj] = acc;
}

// ============================================================================
extern "C" void kernel_launch(void* const* d_in, const int* in_sizes, int n_in,
                              void* d_out, int out_size)
{
    const float* NF    = (const float*)d_in[0];
    const float* EF    = (const float*)d_in[1];
    const float* ADJ   = (const float*)d_in[2];
    const float* LADJ  = (const float*)d_in[3];
    const int*   EIDX  = (const int*)  d_in[4];
    const int*   PAIRS = (const int*)  d_in[5];
    const int*   NOBJ  = (const int*)  d_in[6];
    const int*   NEDG  = (const int*)  d_in[7];
    const float* Wn    = (const float*)d_in[8];
    const float* We    = (const float*)d_in[9];
    const float* Wn2   = (const float*)d_in[10];
    const float* We2   = (const float*)d_in[11];
    const float* scrW1 = (const float*)d_in[12];
    const float* scrb1 = (const float*)d_in[13];
    const float* scrW2 = (const float*)d_in[14];
    const float* scrb2 = (const float*)d_in[15];
    const float* lrW1  = (const float*)d_in[16];
    const float* lrb1  = (const float*)d_in[17];
    const float* lrW2  = (const float*)d_in[18];
    const float* lrb2  = (const float*)d_in[19];
    const float* mrW1  = (const float*)d_in[20];
    const float* mrb1  = (const float*)d_in[21];
    const float* mrW2  = (const float*)d_in[22];
    const float* mrb2  = (const float*)d_in[23];
    float* out = (float*)d_out;

    int *ord, *st;
    cudaGetSymbolAddress((void**)&ord, d_ord);
    cudaGetSymbolAddress((void**)&st,  d_st);

    // stage 1: weight concat + CSR (independent, tiny)
    catw1<<<512, 256>>>(Wn, Wn2, lrW1, scrW1, mrW1, lrb1, scrb1, mrb1);
    csr_kernel<<<B_, 1024>>>(EIDX, ord, st);

    // stage 2: batched GEMM A — XWc(32,K=512) | EgWe gather-fused(128) | Q(64)
    gemm_batchA<<<224, 256>>>(NF, EF, We, We2, EIDX, PAIRS, NOBJ, NEDG);

    // stage 3: merged h | g | pm
    stage3<<<B_ * N_ + B_ * M_ + B_ * P_, 128>>>(ADJ, LADJ, PAIRS, NOBJ, NEDG);

    // stage 3b: deterministic scatter-add via CSR
    agg2_kernel<<<B_ * N_, 128>>>(NOBJ);

    // stage 4: batched GEMM B — hidB(384) | nodeY(96)
    gemm_batchB<<<480, 256>>>();

    // stage 5: fused relu-sum + layer-2 heads -> out
    head2_kernel<<<B_ * P_ / 8, 256>>>(PAIRS, lrW2, lrb2, scrW2, scrb2,
                                       mrW2, mrb2, out);
}

// round 8
// speedup vs baseline: 1.4778x; 1.4778x over previous
#include <cuda_runtime.h>
#include <cstdint>

#define B_   16
#define N_   128
#define M_   1024
#define DN_  512
#define DE_  256
#define WN_  128
#define WE_  128
#define P_   512

// ------------------------- scratch (device globals) -------------------------
__device__ float d_XWc  [B_*N_*256];     // [X@Wn | X@Wn2] (row-masked)
__device__ float d_nemb [B_*N_*256];     // [h | agg] per node
__device__ float d_nodeY[B_*N_*768];     // nemb @ [lrW1|scrW1|mrW1] rows 0:256
__device__ float d_Eg   [B_*M_*DE_];     // gathered edge feats * emask
__device__ float d_EgWe [B_*M_*WE_];     // Eg@We
__device__ float d_g    [B_*M_*WE_];     // relu(L@EgWe)*emask
__device__ float d_EFp  [B_*P_*DE_];     // edge_features at pairs
__device__ float d_pf   [B_*P_*256];     // [Pm | Q] per pair
__device__ float d_hidB [B_*P_*768];     // pf @ W1 rows 256:512 (no bias/relu)
__device__ int   d_ord  [B_*M_];         // CSR edge order by src
__device__ int   d_st   [B_*(N_+1)];     // CSR bucket starts

__device__ __forceinline__ uint32_t f2tf32(float x) {
    uint32_t r;
    asm("cvt.rna.tf32.f32 %0, %1;" : "=r"(r) : "f"(x));
    return r;
}

// ============ TF32 tensor-core GEMM tile (128x128, 8 warps), device fn ======
// BCAT=1: B is dense [K,N] (B0).  BCAT=2: B cols = [B0(128) | B1(128)], each
// source row-major stride 128.  BCAT=3: B cols = [B0|B1|B2], each 256 wide,
// stride 256.  C tile (bx,by) of C = A @ B (+relu, row-mask). K%32==0.
template<int BCAT>
__device__ __forceinline__
void gemm_tile(const float* __restrict__ A,
               const float* __restrict__ B0, const float* __restrict__ B1,
               const float* __restrict__ B2,
               float* __restrict__ C, int K, int N, int ldc, int relu,
               const int* __restrict__ rowcnt, int rpb,
               int bx, int by)
{
    __shared__ uint32_t As[32][136];   // [k][m], pad 8 -> conflict-free frags
    __shared__ uint32_t Bs[32][136];   // [k][n]
    const int tid  = threadIdx.x;
    const int m0 = by * 128, n0 = bx * 128;
    const int lane = tid & 31, warp = tid >> 5;
    const int wm = (warp & 1) * 64, wn = (warp >> 1) * 32;
    const int g  = lane >> 2, t4 = lane & 3;

    const int am = tid >> 1;          // A loader: m row 0..127
    const int ak = (tid & 1) * 4;     //           k quad within 8
    const int bk = tid >> 5;          // B loader: k row 0..7
    const int bn = (tid & 31) * 4;    //           n quad

    const float* Aptr = A + (size_t)(m0 + am) * K + ak;
    // resolve B source/column once (quad never crosses a concat boundary)
    const float* Bsrc; int bstride, bcol;
    {
        int colq = n0 + bn;
        if (BCAT == 1)      { Bsrc = B0; bstride = N; bcol = colq; }
        else if (BCAT == 2) {
            Bsrc = (colq < 128) ? B0 : B1; bstride = 128; bcol = colq & 127;
        } else {
            int th = colq >> 8;
            Bsrc = th == 0 ? B0 : (th == 1 ? B1 : B2);
            bstride = 256; bcol = colq & 255;
        }
    }

    float acc[4][4][4];
#pragma unroll
    for (int a = 0; a < 4; a++)
#pragma unroll
        for (int b = 0; b < 4; b++)
#pragma unroll
            for (int c = 0; c < 4; c++) acc[a][b][c] = 0.0f;

    for (int k0 = 0; k0 < K; k0 += 32) {
#pragma unroll
        for (int ks = 0; ks < 32; ks += 8) {
            float4 v = *(const float4*)(Aptr + k0 + ks);
            As[ks + ak + 0][am] = f2tf32(v.x);
            As[ks + ak + 1][am] = f2tf32(v.y);
            As[ks + ak + 2][am] = f2tf32(v.z);
            As[ks + ak + 3][am] = f2tf32(v.w);
        }
#pragma unroll
        for (int ks = 0; ks < 32; ks += 8) {
            float4 v = *(const float4*)(Bsrc + (size_t)(k0 + ks + bk) * bstride + bcol);
            uint32_t* p = &Bs[ks + bk][bn];
            p[0] = f2tf32(v.x); p[1] = f2tf32(v.y);
            p[2] = f2tf32(v.z); p[3] = f2tf32(v.w);
        }
        __syncthreads();
#pragma unroll
        for (int kk = 0; kk < 32; kk += 8) {
            uint32_t aF[4][4], bF[4][2];
#pragma unroll
            for (int mt = 0; mt < 4; mt++) {
                int mb = wm + mt * 16 + g;
                aF[mt][0] = As[kk + t4    ][mb];
                aF[mt][1] = As[kk + t4    ][mb + 8];
                aF[mt][2] = As[kk + t4 + 4][mb];
                aF[mt][3] = As[kk + t4 + 4][mb + 8];
            }
#pragma unroll
            for (int nt = 0; nt < 4; nt++) {
                int nb = wn + nt * 8 + g;
                bF[nt][0] = Bs[kk + t4    ][nb];
                bF[nt][1] = Bs[kk + t4 + 4][nb];
            }
#pragma unroll
            for (int mt = 0; mt < 4; mt++)
#pragma unroll
                for (int nt = 0; nt < 4; nt++)
                    asm volatile(
                        "mma.sync.aligned.m16n8k8.row.col.f32.tf32.tf32.f32 "
                        "{%0,%1,%2,%3}, {%4,%5,%6,%7}, {%8,%9}, {%0,%1,%2,%3};"
                        : "+f"(acc[mt][nt][0]), "+f"(acc[mt][nt][1]),
                          "+f"(acc[mt][nt][2]), "+f"(acc[mt][nt][3])
                        : "r"(aF[mt][0]), "r"(aF[mt][1]), "r"(aF[mt][2]), "r"(aF[mt][3]),
                          "r"(bF[nt][0]), "r"(bF[nt][1]));
        }
        __syncthreads();
    }

#pragma unroll
    for (int mt = 0; mt < 4; mt++) {
        int row0 = m0 + wm + mt * 16 + g;
        int row1 = row0 + 8;
        float mask0 = 1.0f, mask1 = 1.0f;
        if (rowcnt) {
            if (row0 % rpb >= rowcnt[row0 / rpb]) mask0 = 0.0f;
            if (row1 % rpb >= rowcnt[row1 / rpb]) mask1 = 0.0f;
        }
        float* c0p = C + (size_t)row0 * ldc;
        float* c1p = C + (size_t)row1 * ldc;
#pragma unroll
        for (int nt = 0; nt < 4; nt++) {
            int col = n0 + wn + nt * 8 + 2 * t4;
            float v0 = acc[mt][nt][0], v1 = acc[mt][nt][1];
            float v2 = acc[mt][nt][2], v3 = acc[mt][nt][3];
            if (relu) {
                v0 = fmaxf(v0, 0.f); v1 = fmaxf(v1, 0.f);
                v2 = fmaxf(v2, 0.f); v3 = fmaxf(v3, 0.f);
            }
            float2 w0 = make_float2(v0 * mask0, v1 * mask0);
            float2 w1 = make_float2(v2 * mask1, v3 * mask1);
            *(float2*)(c0p + col) = w0;
            *(float2*)(c1p + col) = w1;
        }
    }
}

// ---- batch A: XWc (32, K=512, cat2) | EgWe (128) | Q (64) ------------------
__global__ __launch_bounds__(256)
void gemm_batchA(const float* __restrict__ NF,
                 const float* __restrict__ Wn, const float* __restrict__ Wn2,
                 const float* __restrict__ We, const float* __restrict__ We2,
                 const int* __restrict__ NOBJ)
{
    int bid = blockIdx.x;
    if (bid < 32) {
        // XWc = mask(NF @ [Wn|Wn2])          [2048 x 256 x 512]
        gemm_tile<2>(NF, Wn, Wn2, nullptr, d_XWc, DN_, 256, 256, 0,
                     NOBJ, N_, bid & 1, bid >> 1);
    } else if (bid < 160) {
        // EgWe = Eg @ We                     [16384 x 128 x 256]
        gemm_tile<1>(d_Eg, We, nullptr, nullptr, d_EgWe, DE_, WE_, WE_, 0,
                     nullptr, 0, 0, bid - 32);
    } else {
        // Q = relu(EFp @ We2) -> pf cols [128:256), ldc=256
        gemm_tile<1>(d_EFp, We2, nullptr, nullptr, d_pf + 128, DE_, WE_, 256, 1,
                     nullptr, 0, 0, bid - 160);
    }
}

// ---- batch B: hidB (384, cat3 rows 256:512) | nodeY (96, cat3 rows 0:256) --
__global__ __launch_bounds__(256)
void gemm_batchB(const float* __restrict__ lrW1, const float* __restrict__ scrW1,
                 const float* __restrict__ mrW1)
{
    int bid = blockIdx.x;
    if (bid < 384) {
        // hidB = pf @ W1[256:512,:] (bias folded into head2)  [8192 x 768 x 256]
        gemm_tile<3>(d_pf, lrW1 + 256 * 256, scrW1 + 256 * 256, mrW1 + 256 * 256,
                     d_hidB, 256, 768, 768, 0, nullptr, 0, bid % 6, bid / 6);
    } else {
        // nodeY = nemb @ W1[0:256,:]                          [2048 x 768 x 256]
        int t = bid - 384;
        gemm_tile<3>(d_nemb, lrW1, scrW1, mrW1,
                     d_nodeY, 256, 768, 768, 0, nullptr, 0, t % 6, t / 6);
    }
}

// ------------------------- Eg gather: Eg[b,m] = EF[b,src,dst]*emask ---------
__global__ void eg_gather(const float* __restrict__ EF, const int* __restrict__ eidx,
                          const int* __restrict__ nedg, float* __restrict__ Eg)
{
    int b = blockIdx.x / M_, m = blockIdx.x % M_;
    int s = eidx[(b * 2 + 0) * M_ + m];
    int d = eidx[(b * 2 + 1) * M_ + m];
    bool on = m < nedg[b];
    const float4* src = (const float4*)(EF + (((size_t)b * N_ + s) * N_ + d) * DE_);
    float4* dst = (float4*)(Eg + ((size_t)b * M_ + m) * DE_);
    float4 z = make_float4(0.f, 0.f, 0.f, 0.f);
    for (int t = threadIdx.x; t < DE_ / 4; t += blockDim.x)
        dst[t] = on ? src[t] : z;
}

// ------------------------- edge feats gathered at pairs ---------------------
__global__ void efp_gather(const float* __restrict__ EF, const int* __restrict__ pairs,
                           float* __restrict__ EFp)
{
    int b = blockIdx.x / P_, p = blockIdx.x % P_;
    int p0 = pairs[((size_t)b * P_ + p) * 2 + 0];
    int p1 = pairs[((size_t)b * P_ + p) * 2 + 1];
    const float4* src = (const float4*)(EF + (((size_t)b * N_ + p0) * N_ + p1) * DE_);
    float4* dst = (float4*)(EFp + ((size_t)b * P_ + p) * DE_);
    for (int t = threadIdx.x; t < DE_ / 4; t += blockDim.x)
        dst[t] = src[t];
}

// --------- h: relu(XW_i + sum_j adj_ij*XW_j)*mask -> nemb cols [0:128) ------
__global__ void h_kernel(const float* __restrict__ adj, const int* __restrict__ nobj)
{
    int b = blockIdx.x / N_, i = blockIdx.x % N_;
    int w = threadIdx.x;                    // 128
    __shared__ float arow[N_];
    arow[w] = adj[((size_t)b * N_ + i) * N_ + w];
    __syncthreads();
    const float* XWb = d_XWc + (size_t)b * N_ * 256;   // cols [0:128)
    float acc = XWb[i * 256 + w];           // identity term (row-masked)
    for (int j = 0; j < N_; j++) {
        float a = arow[j];
        if (a != 0.0f) acc += a * XWb[j * 256 + w];
    }
    d_nemb[((size_t)b * N_ + i) * 256 + w] = (i < nobj[b]) ? fmaxf(acc, 0.0f) : 0.0f;
}

// ----------- g = relu(EgWe_m + sum_k L_mk * EgWe_k) * emask (sparse L) ------
__global__ void g_kernel(const float* __restrict__ ladj, const int* __restrict__ nedg)
{
    int b = blockIdx.x / M_, m = blockIdx.x % M_;
    int w = threadIdx.x;                    // 128
    int lane = w & 31, wp = w >> 5;
    __shared__ int   s_idx[M_];
    __shared__ float s_val[M_];
    __shared__ int   wsum[4];

    const float* Lrow = ladj + ((size_t)b * M_ + m) * M_;
    float4 va = ((const float4*)Lrow)[w * 2];
    float4 vb = ((const float4*)Lrow)[w * 2 + 1];
    float v[8] = {va.x, va.y, va.z, va.w, vb.x, vb.y, vb.z, vb.w};
    int cnt = 0;
#pragma unroll
    for (int t = 0; t < 8; t++)
        if (v[t] != 0.0f) cnt++;

    // parallel exclusive scan of cnt over 128 threads
    int inc = cnt;
#pragma unroll
    for (int d = 1; d < 32; d <<= 1) {
        int t = __shfl_up_sync(0xffffffffu, inc, d);
        if (lane >= d) inc += t;
    }
    if (lane == 31) wsum[wp] = inc;
    __syncthreads();
    int woff = 0;
#pragma unroll
    for (int ww = 0; ww < 4; ww++)
        if (ww < wp) woff += wsum[ww];
    int pos = woff + inc - cnt;             // exclusive prefix
    int base = w * 8;
#pragma unroll
    for (int t = 0; t < 8; t++)
        if (v[t] != 0.0f) { s_idx[pos] = base + t; s_val[pos] = v[t]; pos++; }
    int total = wsum[0] + wsum[1] + wsum[2] + wsum[3];
    __syncthreads();

    const float* Eb = d_EgWe + (size_t)b * M_ * WE_;
    float acc = Eb[m * WE_ + w];            // identity term (Eg row-masked)
    for (int p = 0; p < total; p++)
        acc += s_val[p] * Eb[s_idx[p] * WE_ + w];
    d_g[((size_t)b * M_ + m) * WE_ + w] = (m < nedg[b]) ? fmaxf(acc, 0.0f) : 0.0f;
}

// ---------------- CSR build: bucket edges by src, stable in m ---------------
__global__ __launch_bounds__(1024)
void csr_kernel(const int* __restrict__ eidx,
                int* __restrict__ order, int* __restrict__ start)
{
    int b = blockIdx.x, m = threadIdx.x;    // 1024 threads
    int warp = m >> 5, lane = m & 31;
    __shared__ int ssrc[M_];
    __shared__ int wcnt[32][N_];            // per-warp histogram
    __shared__ int cnt[N_ + 1];
    ssrc[m] = eidx[(b * 2 + 0) * M_ + m];
    for (int i = m; i < 32 * N_; i += 1024) (&wcnt[0][0])[i] = 0;
    __syncthreads();
    int s = ssrc[m];
    unsigned mk = __match_any_sync(0xffffffffu, s);
    int rank_w = __popc(mk & ((1u << lane) - 1));
    if (lane == (__ffs(mk) - 1)) wcnt[warp][s] = __popc(mk);
    __syncthreads();
    int rank = rank_w;
    for (int ww = 0; ww < warp; ww++) rank += wcnt[ww][s];
    if (m < N_) {
        int t = 0;
        for (int ww = 0; ww < 32; ww++) t += wcnt[ww][m];
        cnt[m + 1] = t;
    }
    if (m == 0) cnt[0] = 0;
    __syncthreads();
    if (m == 0)
        for (int i = 1; i <= N_; i++) cnt[i] += cnt[i - 1];
    __syncthreads();
    order[b * M_ + cnt[s] + rank] = m;
    if (m < N_ + 1) start[b * (N_ + 1) + m] = cnt[m];
}

// -------- agg[b,n] = sum_{m in bucket n, ascending m} g[b,m] * nmask --------
__global__ void agg2_kernel(const int* __restrict__ nobj)
{
    int b = blockIdx.x / N_, n = blockIdx.x % N_;
    int w = threadIdx.x;                    // 128
    int s0 = d_st[b * (N_ + 1) + n], s1 = d_st[b * (N_ + 1) + n + 1];
    const float* gb = d_g + (size_t)b * M_ * WE_;
    const int* ob = d_ord + b * M_;
    float acc = 0.0f;
    for (int i = s0; i < s1; i++)
        acc += gb[(size_t)ob[i] * WE_ + w];
    d_nemb[((size_t)b * N_ + n) * 256 + 128 + w] = (n < nobj[b]) ? acc : 0.0f;
}

// -------------------- Pm = relu(XW2[p0]+XW2[p1]) -> pf cols [0:128) ---------
__global__ void pm_kernel(const int* __restrict__ pairs)
{
    int b = blockIdx.x / P_, p = blockIdx.x % P_;
    int w = threadIdx.x;                    // 128
    int p0 = pairs[((size_t)b * P_ + p) * 2 + 0];
    int p1 = pairs[((size_t)b * P_ + p) * 2 + 1];
    const float* xb = d_XWc + (size_t)b * N_ * 256 + 128;   // cols [128:256)
    d_pf[((size_t)b * P_ + p) * 256 + w] =
        fmaxf(xb[(size_t)p0 * 256 + w] + xb[(size_t)p1 * 256 + w], 0.0f);
}

// ------ layer-2 heads: hid = relu(hidB + nY[p0] + nY[p1] + b1) fused --------
__global__ void head2_kernel(const int* __restrict__ pairs,
                             const float* __restrict__ lrb1,
                             const float* __restrict__ scrb1,
                             const float* __restrict__ mrb1,
                             const float* __restrict__ lrW2, const float* __restrict__ lrb2,
                             const float* __restrict__ crW2, const float* __restrict__ crb2,
                             const float* __restrict__ mrW2, const float* __restrict__ mrb2,
                             float* __restrict__ out)
{
    __shared__ float sh[8 * 768];
    __shared__ int sp[16];
    int tid = threadIdx.x;                  // 256
    int blk = blockIdx.x;                   // 8 pairs per block
    if (tid < 16) sp[tid] = pairs[(size_t)blk * 16 + tid];
    __syncthreads();
    int b = (blk * 8) / P_;                 // all 8 pairs share batch (P_%8==0)
    const float* nYb = d_nodeY + (size_t)b * N_ * 768;
    for (int i = tid; i < 8 * 768; i += 256) {
        int lp = i / 768, col = i - lp * 768;
        int gg = blk * 8 + lp;
        float b1 = (col < 256) ? lrb1[col]
                 : (col < 512) ? scrb1[col - 256] : mrb1[col - 512];
        float v = d_hidB[(size_t)gg * 768 + col]
                + nYb[(size_t)sp[lp * 2 + 0] * 768 + col]
                + nYb[(size_t)sp[lp * 2 + 1] * 768 + col] + b1;
        sh[i] = fmaxf(v, 0.0f);
    }
    __syncthreads();
    int lp = tid / 32, j = tid % 32;
    int pr = blk * 8 + lp;
    const float* W2; float bias; int nout, oj; const float* hr; size_t obase;
    if (j < 9)       { W2 = lrW2; oj = j;      bias = lrb2[oj]; nout = 9;  hr = sh + lp * 768;       obase = 0; }
    else if (j < 15) { W2 = crW2; oj = j - 9;  bias = crb2[oj]; nout = 6;  hr = sh + lp * 768 + 256; obase = (size_t)B_ * P_ * 9; }
    else             { W2 = mrW2; oj = j - 15; bias = mrb2[oj]; nout = 17; hr = sh + lp * 768 + 512; obase = (size_t)B_ * P_ * 15; }
    float acc = bias;
#pragma unroll 8
    for (int k = 0; k < 256; k++)
        acc += hr[k] * W2[k * nout + oj];
    out[obase + (size_t)pr * nout + oj] = acc;
}

// ============================================================================
extern "C" void kernel_launch(void* const* d_in, const int* in_sizes, int n_in,
                              void* d_out, int out_size)
{
    const float* NF    = (const float*)d_in[0];
    const float* EF    = (const float*)d_in[1];
    const float* ADJ   = (const float*)d_in[2];
    const float* LADJ  = (const float*)d_in[3];
    const int*   EIDX  = (const int*)  d_in[4];
    const int*   PAIRS = (const int*)  d_in[5];
    const int*   NOBJ  = (const int*)  d_in[6];
    const int*   NEDG  = (const int*)  d_in[7];
    const float* Wn    = (const float*)d_in[8];
    const float* We    = (const float*)d_in[9];
    const float* Wn2   = (const float*)d_in[10];
    const float* We2   = (const float*)d_in[11];
    const float* scrW1 = (const float*)d_in[12];
    const float* scrb1 = (const float*)d_in[13];
    const float* scrW2 = (const float*)d_in[14];
    const float* scrb2 = (const float*)d_in[15];
    const float* lrW1  = (const float*)d_in[16];
    const float* lrb1  = (const float*)d_in[17];
    const float* lrW2  = (const float*)d_in[18];
    const float* lrb2  = (const float*)d_in[19];
    const float* mrW1  = (const float*)d_in[20];
    const float* mrb1  = (const float*)d_in[21];
    const float* mrW2  = (const float*)d_in[22];
    const float* mrb2  = (const float*)d_in[23];
    float* out = (float*)d_out;

    float *Eg, *EFp;
    int *ord, *st;
    cudaGetSymbolAddress((void**)&Eg,  d_Eg);
    cudaGetSymbolAddress((void**)&EFp, d_EFp);
    cudaGetSymbolAddress((void**)&ord, d_ord);
    cudaGetSymbolAddress((void**)&st,  d_st);

    // stage 1: gathers + CSR (independent)
    csr_kernel<<<B_, 1024>>>(EIDX, ord, st);
    eg_gather<<<B_ * M_, 64>>>(EF, EIDX, NEDG, Eg);
    efp_gather<<<B_ * P_, 64>>>(EF, PAIRS, EFp);

    // stage 2: batched GEMM A — XWc(32,K=512,cat2) | EgWe(128) | Q(64)
    gemm_batchA<<<224, 256>>>(NF, Wn, Wn2, We, We2, NOBJ);

    // stage 3: graph convs + pair Pm + deterministic scatter-add
    h_kernel<<<B_ * N_, 128>>>(ADJ, NOBJ);
    g_kernel<<<B_ * M_, 128>>>(LADJ, NEDG);
    pm_kernel<<<B_ * P_, 128>>>(PAIRS);
    agg2_kernel<<<B_ * N_, 128>>>(NOBJ);

    // stage 4: batched GEMM B — hidB(384,cat3) | nodeY(96,cat3)
    gemm_batchB<<<480, 256>>>(lrW1, scrW1, mrW1);

    // stage 5: fused relu-sum (+b1) + layer-2 heads -> out
    head2_kernel<<<B_ * P_ / 8, 256>>>(PAIRS, lrb1, scrb1, mrb1,
                                       lrW2, lrb2, scrW2, scrb2, mrW2, mrb2, out);
}

// round 9
// speedup vs baseline: 1.5393x; 1.0416x over previous
#include <cuda_runtime.h>
#include <cstdint>

#define B_   16
#define N_   128
#define M_   1024
#define DN_  512
#define DE_  256
#define WN_  128
#define WE_  128
#define P_   512

// ------------------------- scratch (device globals) -------------------------
__device__ float d_XWc  [B_*N_*256];     // [X@Wn | X@Wn2] (row-masked)
__device__ float d_nemb [B_*N_*256];     // [h | agg] per node
__device__ float d_nodeY[B_*N_*768];     // nemb @ [lrW1|scrW1|mrW1] rows 0:256
__device__ float d_Eg   [B_*M_*DE_];     // gathered edge feats * emask
__device__ float d_EgWe [B_*M_*WE_];     // Eg@We
__device__ float d_g    [B_*M_*WE_];     // relu(L@EgWe)*emask
__device__ float d_EFp  [B_*P_*DE_];     // edge_features at pairs
__device__ float d_pf   [B_*P_*256];     // [Pm | Q] per pair
__device__ float d_hidB [B_*P_*768];     // pf @ W1 rows 256:512 (no bias/relu)
__device__ int   d_ord  [B_*M_];         // CSR edge order by src
__device__ int   d_st   [B_*(N_+1)];     // CSR bucket starts

__device__ __forceinline__ uint32_t f2tf32(float x) {
    uint32_t r;
    asm("cvt.rna.tf32.f32 %0, %1;" : "=r"(r) : "f"(x));
    return r;
}

// shared tile hoisted out of the template so dispatcher branches share it
struct SmemGemm {
    uint32_t As[32][136];   // [k][m], pad 8 -> conflict-free frags
    uint32_t Bs[32][136];   // [k][n]
};

// ============ TF32 tensor-core GEMM tile (128x128, 8 warps), pipelined ======
// BCAT=1: B dense [K,N].  BCAT=2: B cols = [B0|B1] each 128 wide (stride 128).
// BCAT=3: B cols = [B0|B1|B2] each 256 wide (stride 256).
// C tile (bx,by) of C = A @ B (+relu, row-mask). K%32==0.
template<int BCAT>
__device__ __forceinline__
void gemm_tile(SmemGemm* sm, const float* __restrict__ A,
               const float* __restrict__ B0, const float* __restrict__ B1,
               const float* __restrict__ B2,
               float* __restrict__ C, int K, int N, int ldc, int relu,
               const int* __restrict__ rowcnt, int rpb,
               int bx, int by)
{
    const int tid  = threadIdx.x;
    const int m0 = by * 128, n0 = bx * 128;
    const int lane = tid & 31, warp = tid >> 5;
    const int wm = (warp & 1) * 64, wn = (warp >> 1) * 32;
    const int g  = lane >> 2, t4 = lane & 3;

    const int am = tid >> 1;          // A loader: m row 0..127
    const int ak = (tid & 1) * 4;     //           k quad within 8
    const int bk = tid >> 5;          // B loader: k row 0..7
    const int bn = (tid & 31) * 4;    //           n quad

    const float* Aptr = A + (size_t)(m0 + am) * K + ak;
    const float* Bsrc; int bstride, bcol;
    {
        int colq = n0 + bn;
        if (BCAT == 1)      { Bsrc = B0; bstride = N; bcol = colq; }
        else if (BCAT == 2) {
            Bsrc = (colq < 128) ? B0 : B1; bstride = 128; bcol = colq & 127;
        } else {
            int th = colq >> 8;
            Bsrc = th == 0 ? B0 : (th == 1 ? B1 : B2);
            bstride = 256; bcol = colq & 255;
        }
    }

    float acc[4][4][4];
#pragma unroll
    for (int a = 0; a < 4; a++)
#pragma unroll
        for (int b = 0; b < 4; b++)
#pragma unroll
            for (int c = 0; c < 4; c++) acc[a][b][c] = 0.0f;

    // prologue: prefetch chunk 0
    float4 pa[4], pb[4];
#pragma unroll
    for (int ks = 0; ks < 4; ks++) {
        pa[ks] = *(const float4*)(Aptr + ks * 8);
        pb[ks] = *(const float4*)(Bsrc + (size_t)(ks * 8 + bk) * bstride + bcol);
    }

    for (int k0 = 0; k0 < K; k0 += 32) {
        // commit prefetched chunk to smem
#pragma unroll
        for (int ks = 0; ks < 4; ks++) {
            sm->As[ks * 8 + ak + 0][am] = f2tf32(pa[ks].x);
            sm->As[ks * 8 + ak + 1][am] = f2tf32(pa[ks].y);
            sm->As[ks * 8 + ak + 2][am] = f2tf32(pa[ks].z);
            sm->As[ks * 8 + ak + 3][am] = f2tf32(pa[ks].w);
            uint32_t* p = &sm->Bs[ks * 8 + bk][bn];
            p[0] = f2tf32(pb[ks].x); p[1] = f2tf32(pb[ks].y);
            p[2] = f2tf32(pb[ks].z); p[3] = f2tf32(pb[ks].w);
        }
        __syncthreads();
        // issue loads for next chunk; latency hidden behind the MMA loop
        if (k0 + 32 < K) {
#pragma unroll
            for (int ks = 0; ks < 4; ks++) {
                pa[ks] = *(const float4*)(Aptr + k0 + 32 + ks * 8);
                pb[ks] = *(const float4*)(Bsrc + (size_t)(k0 + 32 + ks * 8 + bk) * bstride + bcol);
            }
        }
#pragma unroll
        for (int kk = 0; kk < 32; kk += 8) {
            uint32_t aF[4][4], bF[4][2];
#pragma unroll
            for (int mt = 0; mt < 4; mt++) {
                int mb = wm + mt * 16 + g;
                aF[mt][0] = sm->As[kk + t4    ][mb];
                aF[mt][1] = sm->As[kk + t4    ][mb + 8];
                aF[mt][2] = sm->As[kk + t4 + 4][mb];
                aF[mt][3] = sm->As[kk + t4 + 4][mb + 8];
            }
#pragma unroll
            for (int nt = 0; nt < 4; nt++) {
                int nb = wn + nt * 8 + g;
                bF[nt][0] = sm->Bs[kk + t4    ][nb];
                bF[nt][1] = sm->Bs[kk + t4 + 4][nb];
            }
#pragma unroll
            for (int mt = 0; mt < 4; mt++)
#pragma unroll
                for (int nt = 0; nt < 4; nt++)
                    asm volatile(
                        "mma.sync.aligned.m16n8k8.row.col.f32.tf32.tf32.f32 "
                        "{%0,%1,%2,%3}, {%4,%5,%6,%7}, {%8,%9}, {%0,%1,%2,%3};"
                        : "+f"(acc[mt][nt][0]), "+f"(acc[mt][nt][1]),
                          "+f"(acc[mt][nt][2]), "+f"(acc[mt][nt][3])
                        : "r"(aF[mt][0]), "r"(aF[mt][1]), "r"(aF[mt][2]), "r"(aF[mt][3]),
                          "r"(bF[nt][0]), "r"(bF[nt][1]));
        }
        __syncthreads();
    }

#pragma unroll
    for (int mt = 0; mt < 4; mt++) {
        int row0 = m0 + wm + mt * 16 + g;
        int row1 = row0 + 8;
        float mask0 = 1.0f, mask1 = 1.0f;
        if (rowcnt) {
            if (row0 % rpb >= rowcnt[row0 / rpb]) mask0 = 0.0f;
            if (row1 % rpb >= rowcnt[row1 / rpb]) mask1 = 0.0f;
        }
        float* c0p = C + (size_t)row0 * ldc;
        float* c1p = C + (size_t)row1 * ldc;
#pragma unroll
        for (int nt = 0; nt < 4; nt++) {
            int col = n0 + wn + nt * 8 + 2 * t4;
            float v0 = acc[mt][nt][0], v1 = acc[mt][nt][1];
            float v2 = acc[mt][nt][2], v3 = acc[mt][nt][3];
            if (relu) {
                v0 = fmaxf(v0, 0.f); v1 = fmaxf(v1, 0.f);
                v2 = fmaxf(v2, 0.f); v3 = fmaxf(v3, 0.f);
            }
            float2 w0 = make_float2(v0 * mask0, v1 * mask0);
            float2 w1 = make_float2(v2 * mask1, v3 * mask1);
            *(float2*)(c0p + col) = w0;
            *(float2*)(c1p + col) = w1;
        }
    }
}

// ---- batch A: XWc (32, K=512, cat2) | EgWe (128) | Q (64) ------------------
__global__ __launch_bounds__(256)
void gemm_batchA(const float* __restrict__ NF,
                 const float* __restrict__ Wn, const float* __restrict__ Wn2,
                 const float* __restrict__ We, const float* __restrict__ We2,
                 const int* __restrict__ NOBJ)
{
    __shared__ SmemGemm sm;
    int bid = blockIdx.x;
    if (bid < 32) {
        // XWc = mask(NF @ [Wn|Wn2])          [2048 x 256 x 512]
        gemm_tile<2>(&sm, NF, Wn, Wn2, nullptr, d_XWc, DN_, 256, 256, 0,
                     NOBJ, N_, bid & 1, bid >> 1);
    } else if (bid < 160) {
        // EgWe = Eg @ We                     [16384 x 128 x 256]
        gemm_tile<1>(&sm, d_Eg, We, nullptr, nullptr, d_EgWe, DE_, WE_, WE_, 0,
                     nullptr, 0, 0, bid - 32);
    } else {
        // Q = relu(EFp @ We2) -> pf cols [128:256), ldc=256
        gemm_tile<1>(&sm, d_EFp, We2, nullptr, nullptr, d_pf + 128, DE_, WE_, 256, 1,
                     nullptr, 0, 0, bid - 160);
    }
}

// ---- batch B: hidB (384, cat3 rows 256:512) | nodeY (96, cat3 rows 0:256) --
__global__ __launch_bounds__(256)
void gemm_batchB(const float* __restrict__ lrW1, const float* __restrict__ scrW1,
                 const float* __restrict__ mrW1)
{
    __shared__ SmemGemm sm;
    int bid = blockIdx.x;
    if (bid < 384) {
        // hidB = pf @ W1[256:512,:] (bias folded into head2)  [8192 x 768 x 256]
        gemm_tile<3>(&sm, d_pf, lrW1 + 256 * 256, scrW1 + 256 * 256, mrW1 + 256 * 256,
                     d_hidB, 256, 768, 768, 0, nullptr, 0, bid % 6, bid / 6);
    } else {
        // nodeY = nemb @ W1[0:256,:]                          [2048 x 768 x 256]
        int t = bid - 384;
        gemm_tile<3>(&sm, d_nemb, lrW1, scrW1, mrW1,
                     d_nodeY, 256, 768, 768, 0, nullptr, 0, t % 6, t / 6);
    }
}

// ------------------------- Eg gather: Eg[b,m] = EF[b,src,dst]*emask ---------
__global__ void eg_gather(const float* __restrict__ EF, const int* __restrict__ eidx,
                          const int* __restrict__ nedg, float* __restrict__ Eg)
{
    int b = blockIdx.x / M_, m = blockIdx.x % M_;
    int s = eidx[(b * 2 + 0) * M_ + m];
    int d = eidx[(b * 2 + 1) * M_ + m];
    bool on = m < nedg[b];
    const float4* src = (const float4*)(EF + (((size_t)b * N_ + s) * N_ + d) * DE_);
    float4* dst = (float4*)(Eg + ((size_t)b * M_ + m) * DE_);
    float4 z = make_float4(0.f, 0.f, 0.f, 0.f);
    for (int t = threadIdx.x; t < DE_ / 4; t += blockDim.x)
        dst[t] = on ? src[t] : z;
}

// ------------------------- edge feats gathered at pairs ---------------------
__global__ void efp_gather(const float* __restrict__ EF, const int* __restrict__ pairs,
                           float* __restrict__ EFp)
{
    int b = blockIdx.x / P_, p = blockIdx.x % P_;
    int p0 = pairs[((size_t)b * P_ + p) * 2 + 0];
    int p1 = pairs[((size_t)b * P_ + p) * 2 + 1];
    const float4* src = (const float4*)(EF + (((size_t)b * N_ + p0) * N_ + p1) * DE_);
    float4* dst = (float4*)(EFp + ((size_t)b * P_ + p) * DE_);
    for (int t = threadIdx.x; t < DE_ / 4; t += blockDim.x)
        dst[t] = src[t];
}

// ------ stage 3 merged: g (16384 first) | h (2048) | pm (8192) --------------
__global__ __launch_bounds__(128)
void stage3(const float* __restrict__ ADJ, const float* __restrict__ LADJ,
            const int* __restrict__ PAIRS, const int* __restrict__ NOBJ,
            const int* __restrict__ NEDG)
{
    __shared__ float s_val[M_];
    __shared__ int   s_idx[M_];
    __shared__ int   wsum[4];
    int bid = blockIdx.x;
    int w = threadIdx.x;                    // 128
    int lane = w & 31, wp = w >> 5;

    if (bid < B_ * M_) {
        // ---- g = relu(EgWe_m + sum_k L_mk*EgWe_k)*emask (sparse L) ----------
        int b = bid / M_, m = bid % M_;
        const float* Lrow = LADJ + ((size_t)b * M_ + m) * M_;
        float4 va = ((const float4*)Lrow)[w * 2];
        float4 vb = ((const float4*)Lrow)[w * 2 + 1];
        float v[8] = {va.x, va.y, va.z, va.w, vb.x, vb.y, vb.z, vb.w};
        int cnt = 0;
#pragma unroll
        for (int t = 0; t < 8; t++)
            if (v[t] != 0.0f) cnt++;
        int inc = cnt;
#pragma unroll
        for (int d = 1; d < 32; d <<= 1) {
            int t = __shfl_up_sync(0xffffffffu, inc, d);
            if (lane >= d) inc += t;
        }
        if (lane == 31) wsum[wp] = inc;
        __syncthreads();
        int woff = 0;
#pragma unroll
        for (int ww = 0; ww < 4; ww++)
            if (ww < wp) woff += wsum[ww];
        int pos = woff + inc - cnt;         // exclusive prefix
        int base = w * 8;
#pragma unroll
        for (int t = 0; t < 8; t++)
            if (v[t] != 0.0f) { s_idx[pos] = base + t; s_val[pos] = v[t]; pos++; }
        int total = wsum[0] + wsum[1] + wsum[2] + wsum[3];
        __syncthreads();

        const float* Eb = d_EgWe + (size_t)b * M_ * WE_;
        float a0 = Eb[m * WE_ + w], a1 = 0.f, a2 = 0.f, a3 = 0.f;
        int p = 0;
        for (; p + 4 <= total; p += 4) {
            a0 += s_val[p]     * Eb[s_idx[p]     * WE_ + w];
            a1 += s_val[p + 1] * Eb[s_idx[p + 1] * WE_ + w];
            a2 += s_val[p + 2] * Eb[s_idx[p + 2] * WE_ + w];
            a3 += s_val[p + 3] * Eb[s_idx[p + 3] * WE_ + w];
        }
        for (; p < total; p++)
            a0 += s_val[p] * Eb[s_idx[p] * WE_ + w];
        float acc = (a0 + a1) + (a2 + a3);
        d_g[((size_t)b * M_ + m) * WE_ + w] =
            (m < NEDG[b]) ? fmaxf(acc, 0.0f) : 0.0f;
    } else if (bid < B_ * M_ + B_ * N_) {
        // ---- h: relu(XW_i + sum_j adj_ij*XW_j)*mask -> nemb cols [0:128) ----
        int t = bid - B_ * M_;
        int b = t / N_, i = t % N_;
        float v = ADJ[((size_t)b * N_ + i) * N_ + w];
        bool nz = v != 0.0f;
        unsigned mk = __ballot_sync(0xffffffffu, nz);
        int rank = __popc(mk & ((1u << lane) - 1));
        if (lane == 0) wsum[wp] = __popc(mk);
        __syncthreads();
        int off = 0;
#pragma unroll
        for (int ww = 0; ww < 4; ww++)
            if (ww < wp) off += wsum[ww];
        if (nz) { s_idx[off + rank] = w; s_val[off + rank] = v; }
        int total = wsum[0] + wsum[1] + wsum[2] + wsum[3];
        __syncthreads();

        const float* XWb = d_XWc + (size_t)b * N_ * 256;   // cols [0:128)
        float a0 = XWb[i * 256 + w], a1 = 0.f, a2 = 0.f, a3 = 0.f;
        int p = 0;
        for (; p + 4 <= total; p += 4) {
            a0 += s_val[p]     * XWb[s_idx[p]     * 256 + w];
            a1 += s_val[p + 1] * XWb[s_idx[p + 1] * 256 + w];
            a2 += s_val[p + 2] * XWb[s_idx[p + 2] * 256 + w];
            a3 += s_val[p + 3] * XWb[s_idx[p + 3] * 256 + w];
        }
        for (; p < total; p++)
            a0 += s_val[p] * XWb[s_idx[p] * 256 + w];
        float acc = (a0 + a1) + (a2 + a3);
        d_nemb[((size_t)b * N_ + i) * 256 + w] =
            (i < NOBJ[b]) ? fmaxf(acc, 0.0f) : 0.0f;
    } else {
        // ---- Pm = relu(XW2[p0]+XW2[p1]) -> pf cols [0:128) ------------------
        int t = bid - B_ * M_ - B_ * N_;
        int b = t / P_, p = t % P_;
        int p0 = PAIRS[((size_t)b * P_ + p) * 2 + 0];
        int p1 = PAIRS[((size_t)b * P_ + p) * 2 + 1];
        const float* xb = d_XWc + (size_t)b * N_ * 256 + 128;   // cols [128:256)
        d_pf[((size_t)b * P_ + p) * 256 + w] =
            fmaxf(xb[(size_t)p0 * 256 + w] + xb[(size_t)p1 * 256 + w], 0.0f);
    }
}

// ---------------- CSR build: bucket edges by src, stable in m ---------------
__global__ __launch_bounds__(1024)
void csr_kernel(const int* __restrict__ eidx,
                int* __restrict__ order, int* __restrict__ start)
{
    int b = blockIdx.x, m = threadIdx.x;    // 1024 threads
    int warp = m >> 5, lane = m & 31;
    __shared__ int ssrc[M_];
    __shared__ int wcnt[32][N_];            // per-warp histogram
    __shared__ int cnt[N_ + 1];
    ssrc[m] = eidx[(b * 2 + 0) * M_ + m];
    for (int i = m; i < 32 * N_; i += 1024) (&wcnt[0][0])[i] = 0;
    __syncthreads();
    int s = ssrc[m];
    unsigned mk = __match_any_sync(0xffffffffu, s);
    int rank_w = __popc(mk & ((1u << lane) - 1));
    if (lane == (__ffs(mk) - 1)) wcnt[warp][s] = __popc(mk);
    __syncthreads();
    int rank = rank_w;
    for (int ww = 0; ww < warp; ww++) rank += wcnt[ww][s];
    if (m < N_) {
        int t = 0;
        for (int ww = 0; ww < 32; ww++) t += wcnt[ww][m];
        cnt[m + 1] = t;
    }
    if (m == 0) cnt[0] = 0;
    __syncthreads();
    if (m == 0)
        for (int i = 1; i <= N_; i++) cnt[i] += cnt[i - 1];
    __syncthreads();
    order[b * M_ + cnt[s] + rank] = m;
    if (m < N_ + 1) start[b * (N_ + 1) + m] = cnt[m];
}

// -------- agg[b,n] = sum_{m in bucket n, ascending m} g[b,m] * nmask --------
__global__ void agg2_kernel(const int* __restrict__ nobj)
{
    int b = blockIdx.x / N_, n = blockIdx.x % N_;
    int w = threadIdx.x;                    // 128
    int s0 = d_st[b * (N_ + 1) + n], s1 = d_st[b * (N_ + 1) + n + 1];
    const float* gb = d_g + (size_t)b * M_ * WE_;
    const int* ob = d_ord + b * M_;
    float acc = 0.0f;
    for (int i = s0; i < s1; i++)
        acc += gb[(size_t)ob[i] * WE_ + w];
    d_nemb[((size_t)b * N_ + n) * 256 + 128 + w] = (n < nobj[b]) ? acc : 0.0f;
}

// ------ layer-2 heads: hid = relu(hidB + nY[p0] + nY[p1] + b1) fused --------
__global__ void head2_kernel(const int* __restrict__ pairs,
                             const float* __restrict__ lrb1,
                             const float* __restrict__ scrb1,
                             const float* __restrict__ mrb1,
                             const float* __restrict__ lrW2, const float* __restrict__ lrb2,
                             const float* __restrict__ crW2, const float* __restrict__ crb2,
                             const float* __restrict__ mrW2, const float* __restrict__ mrb2,
                             float* __restrict__ out)
{
    __shared__ float sh[8 * 768];
    __shared__ int sp[16];
    int tid = threadIdx.x;                  // 256
    int blk = blockIdx.x;                   // 8 pairs per block
    if (tid < 16) sp[tid] = pairs[(size_t)blk * 16 + tid];
    __syncthreads();
    int b = (blk * 8) / P_;                 // all 8 pairs share batch (P_%8==0)
    const float* nYb = d_nodeY + (size_t)b * N_ * 768;
    for (int i = tid; i < 8 * 768; i += 256) {
        int lp = i / 768, col = i - lp * 768;
        int gg = blk * 8 + lp;
        float b1 = (col < 256) ? lrb1[col]
                 : (col < 512) ? scrb1[col - 256] : mrb1[col - 512];
        float v = d_hidB[(size_t)gg * 768 + col]
                + nYb[(size_t)sp[lp * 2 + 0] * 768 + col]
                + nYb[(size_t)sp[lp * 2 + 1] * 768 + col] + b1;
        sh[i] = fmaxf(v, 0.0f);
    }
    __syncthreads();
    int lp = tid / 32, j = tid % 32;
    int pr = blk * 8 + lp;
    const float* W2; float bias; int nout, oj; const float* hr; size_t obase;
    if (j < 9)       { W2 = lrW2; oj = j;      bias = lrb2[oj]; nout = 9;  hr = sh + lp * 768;       obase = 0; }
    else if (j < 15) { W2 = crW2; oj = j - 9;  bias = crb2[oj]; nout = 6;  hr = sh + lp * 768 + 256; obase = (size_t)B_ * P_ * 9; }
    else             { W2 = mrW2; oj = j - 15; bias = mrb2[oj]; nout = 17; hr = sh + lp * 768 + 512; obase = (size_t)B_ * P_ * 15; }
    float acc = bias;
#pragma unroll 8
    for (int k = 0; k < 256; k++)
        acc += hr[k] * W2[k * nout + oj];
    out[obase + (size_t)pr * nout + oj] = acc;
}

// ============================================================================
extern "C" void kernel_launch(void* const* d_in, const int* in_sizes, int n_in,
                              void* d_out, int out_size)
{
    const float* NF    = (const float*)d_in[0];
    const float* EF    = (const float*)d_in[1];
    const float* ADJ   = (const float*)d_in[2];
    const float* LADJ  = (const float*)d_in[3];
    const int*   EIDX  = (const int*)  d_in[4];
    const int*   PAIRS = (const int*)  d_in[5];
    const int*   NOBJ  = (const int*)  d_in[6];
    const int*   NEDG  = (const int*)  d_in[7];
    const float* Wn    = (const float*)d_in[8];
    const float* We    = (const float*)d_in[9];
    const float* Wn2   = (const float*)d_in[10];
    const float* We2   = (const float*)d_in[11];
    const float* scrW1 = (const float*)d_in[12];
    const float* scrb1 = (const float*)d_in[13];
    const float* scrW2 = (const float*)d_in[14];
    const float* scrb2 = (const float*)d_in[15];
    const float* lrW1  = (const float*)d_in[16];
    const float* lrb1  = (const float*)d_in[17];
    const float* lrW2  = (const float*)d_in[18];
    const float* lrb2  = (const float*)d_in[19];
    const float* mrW1  = (const float*)d_in[20];
    const float* mrb1  = (const float*)d_in[21];
    const float* mrW2  = (const float*)d_in[22];
    const float* mrb2  = (const float*)d_in[23];
    float* out = (float*)d_out;

    float *Eg, *EFp;
    int *ord, *st;
    cudaGetSymbolAddress((void**)&Eg,  d_Eg);
    cudaGetSymbolAddress((void**)&EFp, d_EFp);
    cudaGetSymbolAddress((void**)&ord, d_ord);
    cudaGetSymbolAddress((void**)&st,  d_st);

    // stage 1: gathers + CSR (independent)
    csr_kernel<<<B_, 1024>>>(EIDX, ord, st);
    eg_gather<<<B_ * M_, 64>>>(EF, EIDX, NEDG, Eg);
    efp_gather<<<B_ * P_, 64>>>(EF, PAIRS, EFp);

    // stage 2: batched GEMM A — XWc(32,K=512,cat2) | EgWe(128) | Q(64)
    gemm_batchA<<<224, 256>>>(NF, Wn, Wn2, We, We2, NOBJ);

    // stage 3: merged g | h | pm (g's long blocks first), then scatter-add
    stage3<<<B_ * M_ + B_ * N_ + B_ * P_, 128>>>(ADJ, LADJ, PAIRS, NOBJ, NEDG);
    agg2_kernel<<<B_ * N_, 128>>>(NOBJ);

    // stage 4: batched GEMM B — hidB(384,cat3) | nodeY(96,cat3)
    gemm_batchB<<<480, 256>>>(lrW1, scrW1, mrW1);

    // stage 5: fused relu-sum (+b1) + layer-2 heads -> out
    head2_kernel<<<B_ * P_ / 8, 256>>>(PAIRS, lrb1, scrb1, mrb1,
                                       lrW2, lrb2, scrW2, scrb2, mrW2, mrb2, out);
}

// round 10
// speedup vs baseline: 1.5412x; 1.0012x over previous
#include <cuda_runtime.h>
#include <cstdint>

#define B_   16
#define N_   128
#define M_   1024
#define DN_  512
#define DE_  256
#define WN_  128
#define WE_  128
#define P_   512

// ------------------------- scratch (device globals) -------------------------
__device__ float d_XWc  [B_*N_*256];     // [X@Wn | X@Wn2] (row-masked)
__device__ float d_nemb [B_*N_*256];     // [h | agg] per node
__device__ float d_nodeY[B_*N_*768];     // nemb @ [lrW1|scrW1|mrW1] rows 0:256
__device__ float d_Eg   [B_*M_*DE_];     // gathered edge feats * emask
__device__ float d_EgWe [B_*M_*WE_];     // Eg@We
__device__ float d_g    [B_*M_*WE_];     // relu(L@EgWe)*emask
__device__ float d_EFp  [B_*P_*DE_];     // edge_features at pairs
__device__ float d_pf   [B_*P_*256];     // [Pm | Q] per pair
__device__ float d_hidB [B_*P_*768];     // pf @ W1 rows 256:512 (no bias/relu)
__device__ int   d_ord  [B_*M_];         // CSR edge order by src
__device__ int   d_st   [B_*(N_+1)];     // CSR bucket starts

__device__ __forceinline__ uint32_t f2tf32(float x) {
    uint32_t r;
    asm("cvt.rna.tf32.f32 %0, %1;" : "=r"(r) : "f"(x));
    return r;
}

// one pipeline stage of the 128x128 tile (dynamic smem: 2 stages ping-pong)
struct Stage {
    uint32_t As[32][136];   // [k][m], pad 8 -> conflict-free frags
    uint32_t Bs[32][136];   // [k][n]
};

// ======= TF32 tensor-core GEMM tile (128x128, 8 warps), 2-stage pipeline ====
// BCAT=1: B dense [K,N].  BCAT=2: B cols = [B0|B1] each 128 wide (stride 128).
// BCAT=3: B cols = [B0|B1|B2] each 256 wide (stride 256).
// C tile (bx,by) of C = A @ B (+relu, row-mask). K%32==0.
template<int BCAT>
__device__ __forceinline__
void gemm_tile(Stage* st, const float* __restrict__ A,
               const float* __restrict__ B0, const float* __restrict__ B1,
               const float* __restrict__ B2,
               float* __restrict__ C, int K, int N, int ldc, int relu,
               const int* __restrict__ rowcnt, int rpb,
               int bx, int by)
{
    const int tid  = threadIdx.x;
    const int m0 = by * 128, n0 = bx * 128;
    const int lane = tid & 31, warp = tid >> 5;
    const int wm = (warp & 1) * 64, wn = (warp >> 1) * 32;
    const int g  = lane >> 2, t4 = lane & 3;

    const int am = tid >> 1;          // A loader: m row 0..127
    const int ak = (tid & 1) * 4;     //           k quad within 8
    const int bk = tid >> 5;          // B loader: k row 0..7
    const int bn = (tid & 31) * 4;    //           n quad

    const float* Aptr = A + (size_t)(m0 + am) * K + ak;
    const float* Bsrc; int bstride, bcol;
    {
        int colq = n0 + bn;
        if (BCAT == 1)      { Bsrc = B0; bstride = N; bcol = colq; }
        else if (BCAT == 2) {
            Bsrc = (colq < 128) ? B0 : B1; bstride = 128; bcol = colq & 127;
        } else {
            int th = colq >> 8;
            Bsrc = th == 0 ? B0 : (th == 1 ? B1 : B2);
            bstride = 256; bcol = colq & 255;
        }
    }

    float acc[4][4][4];
#pragma unroll
    for (int a = 0; a < 4; a++)
#pragma unroll
        for (int b = 0; b < 4; b++)
#pragma unroll
            for (int c = 0; c < 4; c++) acc[a][b][c] = 0.0f;

    float4 pa[4], pb[4];
    // prologue: chunk 0 -> stage 0, prefetch chunk 1 into regs
#pragma unroll
    for (int ks = 0; ks < 4; ks++) {
        pa[ks] = *(const float4*)(Aptr + ks * 8);
        pb[ks] = *(const float4*)(Bsrc + (size_t)(ks * 8 + bk) * bstride + bcol);
    }
#pragma unroll
    for (int ks = 0; ks < 4; ks++) {
        st[0].As[ks * 8 + ak + 0][am] = f2tf32(pa[ks].x);
        st[0].As[ks * 8 + ak + 1][am] = f2tf32(pa[ks].y);
        st[0].As[ks * 8 + ak + 2][am] = f2tf32(pa[ks].z);
        st[0].As[ks * 8 + ak + 3][am] = f2tf32(pa[ks].w);
        uint32_t* p = &st[0].Bs[ks * 8 + bk][bn];
        p[0] = f2tf32(pb[ks].x); p[1] = f2tf32(pb[ks].y);
        p[2] = f2tf32(pb[ks].z); p[3] = f2tf32(pb[ks].w);
    }
    if (32 < K) {
#pragma unroll
        for (int ks = 0; ks < 4; ks++) {
            pa[ks] = *(const float4*)(Aptr + 32 + ks * 8);
            pb[ks] = *(const float4*)(Bsrc + (size_t)(32 + ks * 8 + bk) * bstride + bcol);
        }
    }
    __syncthreads();

    int s = 0;
    for (int k0 = 0; k0 < K; k0 += 32, s ^= 1) {
        // stage s holds chunk k0 (readable); regs hold chunk k0+32
        if (k0 + 32 < K) {
            Stage& nx = st[s ^ 1];
#pragma unroll
            for (int ks = 0; ks < 4; ks++) {
                nx.As[ks * 8 + ak + 0][am] = f2tf32(pa[ks].x);
                nx.As[ks * 8 + ak + 1][am] = f2tf32(pa[ks].y);
                nx.As[ks * 8 + ak + 2][am] = f2tf32(pa[ks].z);
                nx.As[ks * 8 + ak + 3][am] = f2tf32(pa[ks].w);
                uint32_t* p = &nx.Bs[ks * 8 + bk][bn];
                p[0] = f2tf32(pb[ks].x); p[1] = f2tf32(pb[ks].y);
                p[2] = f2tf32(pb[ks].z); p[3] = f2tf32(pb[ks].w);
            }
            if (k0 + 64 < K) {
#pragma unroll
                for (int ks = 0; ks < 4; ks++) {
                    pa[ks] = *(const float4*)(Aptr + k0 + 64 + ks * 8);
                    pb[ks] = *(const float4*)(Bsrc + (size_t)(k0 + 64 + ks * 8 + bk) * bstride + bcol);
                }
            }
        }
        Stage& cu = st[s];
#pragma unroll
        for (int kk = 0; kk < 32; kk += 8) {
            uint32_t aF[4][4], bF[4][2];
#pragma unroll
            for (int mt = 0; mt < 4; mt++) {
                int mb = wm + mt * 16 + g;
                aF[mt][0] = cu.As[kk + t4    ][mb];
                aF[mt][1] = cu.As[kk + t4    ][mb + 8];
                aF[mt][2] = cu.As[kk + t4 + 4][mb];
                aF[mt][3] = cu.As[kk + t4 + 4][mb + 8];
            }
#pragma unroll
            for (int nt = 0; nt < 4; nt++) {
                int nb = wn + nt * 8 + g;
                bF[nt][0] = cu.Bs[kk + t4    ][nb];
                bF[nt][1] = cu.Bs[kk + t4 + 4][nb];
            }
#pragma unroll
            for (int mt = 0; mt < 4; mt++)
#pragma unroll
                for (int nt = 0; nt < 4; nt++)
                    asm volatile(
                        "mma.sync.aligned.m16n8k8.row.col.f32.tf32.tf32.f32 "
                        "{%0,%1,%2,%3}, {%4,%5,%6,%7}, {%8,%9}, {%0,%1,%2,%3};"
                        : "+f"(acc[mt][nt][0]), "+f"(acc[mt][nt][1]),
                          "+f"(acc[mt][nt][2]), "+f"(acc[mt][nt][3])
                        : "r"(aF[mt][0]), "r"(aF[mt][1]), "r"(aF[mt][2]), "r"(aF[mt][3]),
                          "r"(bF[nt][0]), "r"(bF[nt][1]));
        }
        __syncthreads();   // STS(s^1) complete; MMA(s) done -> s reusable next iter
    }

#pragma unroll
    for (int mt = 0; mt < 4; mt++) {
        int row0 = m0 + wm + mt * 16 + g;
        int row1 = row0 + 8;
        float mask0 = 1.0f, mask1 = 1.0f;
        if (rowcnt) {
            if (row0 % rpb >= rowcnt[row0 / rpb]) mask0 = 0.0f;
            if (row1 % rpb >= rowcnt[row1 / rpb]) mask1 = 0.0f;
        }
        float* c0p = C + (size_t)row0 * ldc;
        float* c1p = C + (size_t)row1 * ldc;
#pragma unroll
        for (int nt = 0; nt < 4; nt++) {
            int col = n0 + wn + nt * 8 + 2 * t4;
            float v0 = acc[mt][nt][0], v1 = acc[mt][nt][1];
            float v2 = acc[mt][nt][2], v3 = acc[mt][nt][3];
            if (relu) {
                v0 = fmaxf(v0, 0.f); v1 = fmaxf(v1, 0.f);
                v2 = fmaxf(v2, 0.f); v3 = fmaxf(v3, 0.f);
            }
            float2 w0 = make_float2(v0 * mask0, v1 * mask0);
            float2 w1 = make_float2(v2 * mask1, v3 * mask1);
            *(float2*)(c0p + col) = w0;
            *(float2*)(c1p + col) = w1;
        }
    }
}

// ---- batch A: XWc (32, K=512, cat2) | EgWe (128) | Q (64) ------------------
__global__ __launch_bounds__(256)
void gemm_batchA(const float* __restrict__ NF,
                 const float* __restrict__ Wn, const float* __restrict__ Wn2,
                 const float* __restrict__ We, const float* __restrict__ We2,
                 const int* __restrict__ NOBJ)
{
    extern __shared__ Stage st[];
    int bid = blockIdx.x;
    if (bid < 32) {
        // XWc = mask(NF @ [Wn|Wn2])          [2048 x 256 x 512]
        gemm_tile<2>(st, NF, Wn, Wn2, nullptr, d_XWc, DN_, 256, 256, 0,
                     NOBJ, N_, bid & 1, bid >> 1);
    } else if (bid < 160) {
        // EgWe = Eg @ We                     [16384 x 128 x 256]
        gemm_tile<1>(st, d_Eg, We, nullptr, nullptr, d_EgWe, DE_, WE_, WE_, 0,
                     nullptr, 0, 0, bid - 32);
    } else {
        // Q = relu(EFp @ We2) -> pf cols [128:256), ldc=256
        gemm_tile<1>(st, d_EFp, We2, nullptr, nullptr, d_pf + 128, DE_, WE_, 256, 1,
                     nullptr, 0, 0, bid - 160);
    }
}

// ---- batch B: hidB (384, cat3 rows 256:512) | nodeY (96, cat3 rows 0:256) --
__global__ __launch_bounds__(256)
void gemm_batchB(const float* __restrict__ lrW1, const float* __restrict__ scrW1,
                 const float* __restrict__ mrW1)
{
    extern __shared__ Stage st[];
    int bid = blockIdx.x;
    if (bid < 384) {
        // hidB = pf @ W1[256:512,:] (bias folded into head2)  [8192 x 768 x 256]
        gemm_tile<3>(st, d_pf, lrW1 + 256 * 256, scrW1 + 256 * 256, mrW1 + 256 * 256,
                     d_hidB, 256, 768, 768, 0, nullptr, 0, bid % 6, bid / 6);
    } else {
        // nodeY = nemb @ W1[0:256,:]                          [2048 x 768 x 256]
        int t = bid - 384;
        gemm_tile<3>(st, d_nemb, lrW1, scrW1, mrW1,
                     d_nodeY, 256, 768, 768, 0, nullptr, 0, t % 6, t / 6);
    }
}

// ------------------------- Eg gather: Eg[b,m] = EF[b,src,dst]*emask ---------
__global__ void eg_gather(const float* __restrict__ EF, const int* __restrict__ eidx,
                          const int* __restrict__ nedg, float* __restrict__ Eg)
{
    int b = blockIdx.x / M_, m = blockIdx.x % M_;
    int s = eidx[(b * 2 + 0) * M_ + m];
    int d = eidx[(b * 2 + 1) * M_ + m];
    bool on = m < nedg[b];
    const float4* src = (const float4*)(EF + (((size_t)b * N_ + s) * N_ + d) * DE_);
    float4* dst = (float4*)(Eg + ((size_t)b * M_ + m) * DE_);
    float4 z = make_float4(0.f, 0.f, 0.f, 0.f);
    for (int t = threadIdx.x; t < DE_ / 4; t += blockDim.x)
        dst[t] = on ? src[t] : z;
}

// ------------------------- edge feats gathered at pairs ---------------------
__global__ void efp_gather(const float* __restrict__ EF, const int* __restrict__ pairs,
                           float* __restrict__ EFp)
{
    int b = blockIdx.x / P_, p = blockIdx.x % P_;
    int p0 = pairs[((size_t)b * P_ + p) * 2 + 0];
    int p1 = pairs[((size_t)b * P_ + p) * 2 + 1];
    const float4* src = (const float4*)(EF + (((size_t)b * N_ + p0) * N_ + p1) * DE_);
    float4* dst = (float4*)(EFp + ((size_t)b * P_ + p) * DE_);
    for (int t = threadIdx.x; t < DE_ / 4; t += blockDim.x)
        dst[t] = src[t];
}

// ------ stage 3 merged: g (16384 first) | h (2048) | pm (8192) --------------
__global__ __launch_bounds__(128)
void stage3(const float* __restrict__ ADJ, const float* __restrict__ LADJ,
            const int* __restrict__ PAIRS, const int* __restrict__ NOBJ,
            const int* __restrict__ NEDG)
{
    __shared__ float s_val[M_];
    __shared__ int   s_idx[M_];
    __shared__ int   wsum[4];
    int bid = blockIdx.x;
    int w = threadIdx.x;                    // 128
    int lane = w & 31, wp = w >> 5;

    if (bid < B_ * M_) {
        // ---- g = relu(EgWe_m + sum_k L_mk*EgWe_k)*emask (sparse L) ----------
        int b = bid / M_, m = bid % M_;
        const float* Lrow = LADJ + ((size_t)b * M_ + m) * M_;
        float4 va = ((const float4*)Lrow)[w * 2];
        float4 vb = ((const float4*)Lrow)[w * 2 + 1];
        float v[8] = {va.x, va.y, va.z, va.w, vb.x, vb.y, vb.z, vb.w};
        int cnt = 0;
#pragma unroll
        for (int t = 0; t < 8; t++)
            if (v[t] != 0.0f) cnt++;
        int inc = cnt;
#pragma unroll
        for (int d = 1; d < 32; d <<= 1) {
            int t = __shfl_up_sync(0xffffffffu, inc, d);
            if (lane >= d) inc += t;
        }
        if (lane == 31) wsum[wp] = inc;
        __syncthreads();
        int woff = 0;
#pragma unroll
        for (int ww = 0; ww < 4; ww++)
            if (ww < wp) woff += wsum[ww];
        int pos = woff + inc - cnt;         // exclusive prefix
        int base = w * 8;
#pragma unroll
        for (int t = 0; t < 8; t++)
            if (v[t] != 0.0f) { s_idx[pos] = base + t; s_val[pos] = v[t]; pos++; }
        int total = wsum[0] + wsum[1] + wsum[2] + wsum[3];
        __syncthreads();

        const float* Eb = d_EgWe + (size_t)b * M_ * WE_;
        float a0 = Eb[m * WE_ + w], a1 = 0.f, a2 = 0.f, a3 = 0.f;
        int p = 0;
        for (; p + 4 <= total; p += 4) {
            a0 += s_val[p]     * Eb[s_idx[p]     * WE_ + w];
            a1 += s_val[p + 1] * Eb[s_idx[p + 1] * WE_ + w];
            a2 += s_val[p + 2] * Eb[s_idx[p + 2] * WE_ + w];
            a3 += s_val[p + 3] * Eb[s_idx[p + 3] * WE_ + w];
        }
        for (; p < total; p++)
            a0 += s_val[p] * Eb[s_idx[p] * WE_ + w];
        float acc = (a0 + a1) + (a2 + a3);
        d_g[((size_t)b * M_ + m) * WE_ + w] =
            (m < NEDG[b]) ? fmaxf(acc, 0.0f) : 0.0f;
    } else if (bid < B_ * M_ + B_ * N_) {
        // ---- h: relu(XW_i + sum_j adj_ij*XW_j)*mask -> nemb cols [0:128) ----
        int t = bid - B_ * M_;
        int b = t / N_, i = t % N_;
        float v = ADJ[((size_t)b * N_ + i) * N_ + w];
        bool nz = v != 0.0f;
        unsigned mk = __ballot_sync(0xffffffffu, nz);
        int rank = __popc(mk & ((1u << lane) - 1));
        if (lane == 0) wsum[wp] = __popc(mk);
        __syncthreads();
        int off = 0;
#pragma unroll
        for (int ww = 0; ww < 4; ww++)
            if (ww < wp) off += wsum[ww];
        if (nz) { s_idx[off + rank] = w; s_val[off + rank] = v; }
        int total = wsum[0] + wsum[1] + wsum[2] + wsum[3];
        __syncthreads();

        const float* XWb = d_XWc + (size_t)b * N_ * 256;   // cols [0:128)
        float a0 = XWb[i * 256 + w], a1 = 0.f, a2 = 0.f, a3 = 0.f;
        int p = 0;
        for (; p + 4 <= total; p += 4) {
            a0 += s_val[p]     * XWb[s_idx[p]     * 256 + w];
            a1 += s_val[p + 1] * XWb[s_idx[p + 1] * 256 + w];
            a2 += s_val[p + 2] * XWb[s_idx[p + 2] * 256 + w];
            a3 += s_val[p + 3] * XWb[s_idx[p + 3] * 256 + w];
        }
        for (; p < total; p++)
            a0 += s_val[p] * XWb[s_idx[p] * 256 + w];
        float acc = (a0 + a1) + (a2 + a3);
        d_nemb[((size_t)b * N_ + i) * 256 + w] =
            (i < NOBJ[b]) ? fmaxf(acc, 0.0f) : 0.0f;
    } else {
        // ---- Pm = relu(XW2[p0]+XW2[p1]) -> pf cols [0:128) ------------------
        int t = bid - B_ * M_ - B_ * N_;
        int b = t / P_, p = t % P_;
        int p0 = PAIRS[((size_t)b * P_ + p) * 2 + 0];
        int p1 = PAIRS[((size_t)b * P_ + p) * 2 + 1];
        const float* xb = d_XWc + (size_t)b * N_ * 256 + 128;   // cols [128:256)
        d_pf[((size_t)b * P_ + p) * 256 + w] =
            fmaxf(xb[(size_t)p0 * 256 + w] + xb[(size_t)p1 * 256 + w], 0.0f);
    }
}

// ---------------- CSR build: bucket edges by src, stable in m ---------------
__global__ __launch_bounds__(1024)
void csr_kernel(const int* __restrict__ eidx,
                int* __restrict__ order, int* __restrict__ start)
{
    int b = blockIdx.x, m = threadIdx.x;    // 1024 threads
    int warp = m >> 5, lane = m & 31;
    __shared__ int ssrc[M_];
    __shared__ int wcnt[32][N_];            // per-warp histogram
    __shared__ int cnt[N_ + 1];
    ssrc[m] = eidx[(b * 2 + 0) * M_ + m];
    for (int i = m; i < 32 * N_; i += 1024) (&wcnt[0][0])[i] = 0;
    __syncthreads();
    int s = ssrc[m];
    unsigned mk = __match_any_sync(0xffffffffu, s);
    int rank_w = __popc(mk & ((1u << lane) - 1));
    if (lane == (__ffs(mk) - 1)) wcnt[warp][s] = __popc(mk);
    __syncthreads();
    int rank = rank_w;
    for (int ww = 0; ww < warp; ww++) rank += wcnt[ww][s];
    if (m < N_) {
        int t = 0;
        for (int ww = 0; ww < 32; ww++) t += wcnt[ww][m];
        cnt[m + 1] = t;
    }
    if (m == 0) cnt[0] = 0;
    __syncthreads();
    if (m == 0)
        for (int i = 1; i <= N_; i++) cnt[i] += cnt[i - 1];
    __syncthreads();
    order[b * M_ + cnt[s] + rank] = m;
    if (m < N_ + 1) start[b * (N_ + 1) + m] = cnt[m];
}

// -------- agg[b,n] = sum_{m in bucket n, ascending m} g[b,m] * nmask --------
__global__ void agg2_kernel(const int* __restrict__ nobj)
{
    int b = blockIdx.x / N_, n = blockIdx.x % N_;
    int w = threadIdx.x;                    // 128
    int s0 = d_st[b * (N_ + 1) + n], s1 = d_st[b * (N_ + 1) + n + 1];
    const float* gb = d_g + (size_t)b * M_ * WE_;
    const int* ob = d_ord + b * M_;
    float acc = 0.0f;
    for (int i = s0; i < s1; i++)
        acc += gb[(size_t)ob[i] * WE_ + w];
    d_nemb[((size_t)b * N_ + n) * 256 + 128 + w] = (n < nobj[b]) ? acc : 0.0f;
}

// ------ layer-2 heads: hid = relu(hidB + nY[p0] + nY[p1] + b1) fused --------
__global__ void head2_kernel(const int* __restrict__ pairs,
                             const float* __restrict__ lrb1,
                             const float* __restrict__ scrb1,
                             const float* __restrict__ mrb1,
                             const float* __restrict__ lrW2, const float* __restrict__ lrb2,
                             const float* __restrict__ crW2, const float* __restrict__ crb2,
                             const float* __restrict__ mrW2, const float* __restrict__ mrb2,
                             float* __restrict__ out)
{
    __shared__ float sh[8 * 768];
    __shared__ int sp[16];
    int tid = threadIdx.x;                  // 256
    int blk = blockIdx.x;                   // 8 pairs per block
    if (tid < 16) sp[tid] = pairs[(size_t)blk * 16 + tid];
    __syncthreads();
    int b = (blk * 8) / P_;                 // all 8 pairs share batch (P_%8==0)
    const float* nYb = d_nodeY + (size_t)b * N_ * 768;
    for (int i = tid; i < 8 * 768; i += 256) {
        int lp = i / 768, col = i - lp * 768;
        int gg = blk * 8 + lp;
        float b1 = (col < 256) ? lrb1[col]
                 : (col < 512) ? scrb1[col - 256] : mrb1[col - 512];
        float v = d_hidB[(size_t)gg * 768 + col]
                + nYb[(size_t)sp[lp * 2 + 0] * 768 + col]
                + nYb[(size_t)sp[lp * 2 + 1] * 768 + col] + b1;
        sh[i] = fmaxf(v, 0.0f);
    }
    __syncthreads();
    int lp = tid / 32, j = tid % 32;
    int pr = blk * 8 + lp;
    const float* W2; float bias; int nout, oj; const float* hr; size_t obase;
    if (j < 9)       { W2 = lrW2; oj = j;      bias = lrb2[oj]; nout = 9;  hr = sh + lp * 768;       obase = 0; }
    else if (j < 15) { W2 = crW2; oj = j - 9;  bias = crb2[oj]; nout = 6;  hr = sh + lp * 768 + 256; obase = (size_t)B_ * P_ * 9; }
    else             { W2 = mrW2; oj = j - 15; bias = mrb2[oj]; nout = 17; hr = sh + lp * 768 + 512; obase = (size_t)B_ * P_ * 15; }
    float acc = bias;
#pragma unroll 8
    for (int k = 0; k < 256; k++)
        acc += hr[k] * W2[k * nout + oj];
    out[obase + (size_t)pr * nout + oj] = acc;
}

// ============================================================================
extern "C" void kernel_launch(void* const* d_in, const int* in_sizes, int n_in,
                              void* d_out, int out_size)
{
    const float* NF    = (const float*)d_in[0];
    const float* EF    = (const float*)d_in[1];
    const float* ADJ   = (const float*)d_in[2];
    const float* LADJ  = (const float*)d_in[3];
    const int*   EIDX  = (const int*)  d_in[4];
    const int*   PAIRS = (const int*)  d_in[5];
    const int*   NOBJ  = (const int*)  d_in[6];
    const int*   NEDG  = (const int*)  d_in[7];
    const float* Wn    = (const float*)d_in[8];
    const float* We    = (const float*)d_in[9];
    const float* Wn2   = (const float*)d_in[10];
    const float* We2   = (const float*)d_in[11];
    const float* scrW1 = (const float*)d_in[12];
    const float* scrb1 = (const float*)d_in[13];
    const float* scrW2 = (const float*)d_in[14];
    const float* scrb2 = (const float*)d_in[15];
    const float* lrW1  = (const float*)d_in[16];
    const float* lrb1  = (const float*)d_in[17];
    const float* lrW2  = (const float*)d_in[18];
    const float* lrb2  = (const float*)d_in[19];
    const float* mrW1  = (const float*)d_in[20];
    const float* mrb1  = (const float*)d_in[21];
    const float* mrW2  = (const float*)d_in[22];
    const float* mrb2  = (const float*)d_in[23];
    float* out = (float*)d_out;

    float *Eg, *EFp;
    int *ord, *st;
    cudaGetSymbolAddress((void**)&Eg,  d_Eg);
    cudaGetSymbolAddress((void**)&EFp, d_EFp);
    cudaGetSymbolAddress((void**)&ord, d_ord);
    cudaGetSymbolAddress((void**)&st,  d_st);

    // dynamic smem opt-in for the 2-stage GEMM pipeline (non-stream call; safe
    // under graph capture, executes immediately, idempotent)
    const int smemBytes = 2 * (int)sizeof(Stage);   // 69632
    cudaFuncSetAttribute(gemm_batchA, cudaFuncAttributeMaxDynamicSharedMemorySize, smemBytes);
    cudaFuncSetAttribute(gemm_batchB, cudaFuncAttributeMaxDynamicSharedMemorySize, smemBytes);

    // stage 1: gathers + CSR (independent)
    csr_kernel<<<B_, 1024>>>(EIDX, ord, st);
    eg_gather<<<B_ * M_, 64>>>(EF, EIDX, NEDG, Eg);
    efp_gather<<<B_ * P_, 64>>>(EF, PAIRS, EFp);

    // stage 2: batched GEMM A — XWc(32,K=512,cat2) | EgWe(128) | Q(64)
    gemm_batchA<<<224, 256, smemBytes>>>(NF, Wn, Wn2, We, We2, NOBJ);

    // stage 3: merged g | h | pm (g's long blocks first), then scatter-add
    stage3<<<B_ * M_ + B_ * N_ + B_ * P_, 128>>>(ADJ, LADJ, PAIRS, NOBJ, NEDG);
    agg2_kernel<<<B_ * N_, 128>>>(NOBJ);

    // stage 4: batched GEMM B — hidB(384,cat3) | nodeY(96,cat3)
    gemm_batchB<<<480, 256, smemBytes>>>(lrW1, scrW1, mrW1);

    // stage 5: fused relu-sum (+b1) + layer-2 heads -> out
    head2_kernel<<<B_ * P_ / 8, 256>>>(PAIRS, lrb1, scrb1, mrb1,
                                       lrW2, lrb2, scrW2, scrb2, mrW2, mrb2, out);
}

// round 11
// speedup vs baseline: 1.5840x; 1.0278x over previous
#include <cuda_runtime.h>
#include <cstdint>

#define B_   16
#define N_   128
#define M_   1024
#define DN_  512
#define DE_  256
#define WN_  128
#define WE_  128
#define P_   512

// ------------------------- scratch (device globals) -------------------------
__device__ float d_XWc  [B_*N_*256];     // [X@Wn | X@Wn2] (row-masked)
__device__ float d_nemb [B_*N_*256];     // [h | agg] per node
__device__ float d_nodeY[B_*N_*768];     // nemb @ [lrW1|scrW1|mrW1] rows 0:256
__device__ float d_Eg   [B_*M_*DE_];     // gathered edge feats * emask
__device__ float d_EgWe [B_*M_*WE_];     // Eg@We
__device__ float d_g    [B_*M_*WE_];     // relu(L@EgWe)*emask
__device__ float d_EFp  [B_*P_*DE_];     // edge_features at pairs
__device__ float d_pf   [B_*P_*256];     // [Pm | Q] per pair
__device__ float d_hidB [B_*P_*768];     // pf @ W1 rows 256:512 (no bias/relu)
__device__ int   d_ord  [B_*M_];         // CSR edge order by src
__device__ int   d_st   [B_*(N_+1)];     // CSR bucket starts

__device__ __forceinline__ uint32_t f2tf32(float x) {
    uint32_t r;
    asm("cvt.rna.tf32.f32 %0, %1;" : "=r"(r) : "f"(x));
    return r;
}

// one pipeline stage of the 128x128 tile (dynamic smem: 2 stages ping-pong)
struct Stage {
    uint32_t As[32][136];   // [k][m], pad 8 -> conflict-free frags
    uint32_t Bs[32][136];   // [k][n]
};

// ======= TF32 tensor-core GEMM tile (128x128, 8 warps), 2-stage pipeline ====
// BCAT=1: B dense [K,N].  BCAT=2: B cols = [B0|B1] each 128 wide (stride 128).
// BCAT=3: B cols = [B0|B1|B2] each 256 wide (stride 256).
// C tile (bx,by) of C = A @ B (+relu, row-mask). K%32==0.
template<int BCAT>
__device__ __forceinline__
void gemm_tile(Stage* st, const float* __restrict__ A,
               const float* __restrict__ B0, const float* __restrict__ B1,
               const float* __restrict__ B2,
               float* __restrict__ C, int K, int N, int ldc, int relu,
               const int* __restrict__ rowcnt, int rpb,
               int bx, int by)
{
    const int tid  = threadIdx.x;
    const int m0 = by * 128, n0 = bx * 128;
    const int lane = tid & 31, warp = tid >> 5;
    const int wm = (warp & 1) * 64, wn = (warp >> 1) * 32;
    const int g  = lane >> 2, t4 = lane & 3;

    const int am = tid >> 1;          // A loader: m row 0..127
    const int ak = (tid & 1) * 4;     //           k quad within 8
    const int bk = tid >> 5;          // B loader: k row 0..7
    const int bn = (tid & 31) * 4;    //           n quad

    const float* Aptr = A + (size_t)(m0 + am) * K + ak;
    const float* Bsrc; int bstride, bcol;
    {
        int colq = n0 + bn;
        if (BCAT == 1)      { Bsrc = B0; bstride = N; bcol = colq; }
        else if (BCAT == 2) {
            Bsrc = (colq < 128) ? B0 : B1; bstride = 128; bcol = colq & 127;
        } else {
            int th = colq >> 8;
            Bsrc = th == 0 ? B0 : (th == 1 ? B1 : B2);
            bstride = 256; bcol = colq & 255;
        }
    }

    float acc[4][4][4];
#pragma unroll
    for (int a = 0; a < 4; a++)
#pragma unroll
        for (int b = 0; b < 4; b++)
#pragma unroll
            for (int c = 0; c < 4; c++) acc[a][b][c] = 0.0f;

    float4 pa[4], pb[4];
    // prologue: chunk 0 -> stage 0, prefetch chunk 1 into regs
#pragma unroll
    for (int ks = 0; ks < 4; ks++) {
        pa[ks] = *(const float4*)(Aptr + ks * 8);
        pb[ks] = *(const float4*)(Bsrc + (size_t)(ks * 8 + bk) * bstride + bcol);
    }
#pragma unroll
    for (int ks = 0; ks < 4; ks++) {
        st[0].As[ks * 8 + ak + 0][am] = f2tf32(pa[ks].x);
        st[0].As[ks * 8 + ak + 1][am] = f2tf32(pa[ks].y);
        st[0].As[ks * 8 + ak + 2][am] = f2tf32(pa[ks].z);
        st[0].As[ks * 8 + ak + 3][am] = f2tf32(pa[ks].w);
        uint32_t* p = &st[0].Bs[ks * 8 + bk][bn];
        p[0] = f2tf32(pb[ks].x); p[1] = f2tf32(pb[ks].y);
        p[2] = f2tf32(pb[ks].z); p[3] = f2tf32(pb[ks].w);
    }
    if (32 < K) {
#pragma unroll
        for (int ks = 0; ks < 4; ks++) {
            pa[ks] = *(const float4*)(Aptr + 32 + ks * 8);
            pb[ks] = *(const float4*)(Bsrc + (size_t)(32 + ks * 8 + bk) * bstride + bcol);
        }
    }
    __syncthreads();

    int s = 0;
    for (int k0 = 0; k0 < K; k0 += 32, s ^= 1) {
        // stage s holds chunk k0 (readable); regs hold chunk k0+32
        if (k0 + 32 < K) {
            Stage& nx = st[s ^ 1];
#pragma unroll
            for (int ks = 0; ks < 4; ks++) {
                nx.As[ks * 8 + ak + 0][am] = f2tf32(pa[ks].x);
                nx.As[ks * 8 + ak + 1][am] = f2tf32(pa[ks].y);
                nx.As[ks * 8 + ak + 2][am] = f2tf32(pa[ks].z);
                nx.As[ks * 8 + ak + 3][am] = f2tf32(pa[ks].w);
                uint32_t* p = &nx.Bs[ks * 8 + bk][bn];
                p[0] = f2tf32(pb[ks].x); p[1] = f2tf32(pb[ks].y);
                p[2] = f2tf32(pb[ks].z); p[3] = f2tf32(pb[ks].w);
            }
            if (k0 + 64 < K) {
#pragma unroll
                for (int ks = 0; ks < 4; ks++) {
                    pa[ks] = *(const float4*)(Aptr + k0 + 64 + ks * 8);
                    pb[ks] = *(const float4*)(Bsrc + (size_t)(k0 + 64 + ks * 8 + bk) * bstride + bcol);
                }
            }
        }
        Stage& cu = st[s];
#pragma unroll
        for (int kk = 0; kk < 32; kk += 8) {
            uint32_t aF[4][4], bF[4][2];
#pragma unroll
            for (int mt = 0; mt < 4; mt++) {
                int mb = wm + mt * 16 + g;
                aF[mt][0] = cu.As[kk + t4    ][mb];
                aF[mt][1] = cu.As[kk + t4    ][mb + 8];
                aF[mt][2] = cu.As[kk + t4 + 4][mb];
                aF[mt][3] = cu.As[kk + t4 + 4][mb + 8];
            }
#pragma unroll
            for (int nt = 0; nt < 4; nt++) {
                int nb = wn + nt * 8 + g;
                bF[nt][0] = cu.Bs[kk + t4    ][nb];
                bF[nt][1] = cu.Bs[kk + t4 + 4][nb];
            }
#pragma unroll
            for (int mt = 0; mt < 4; mt++)
#pragma unroll
                for (int nt = 0; nt < 4; nt++)
                    asm volatile(
                        "mma.sync.aligned.m16n8k8.row.col.f32.tf32.tf32.f32 "
                        "{%0,%1,%2,%3}, {%4,%5,%6,%7}, {%8,%9}, {%0,%1,%2,%3};"
                        : "+f"(acc[mt][nt][0]), "+f"(acc[mt][nt][1]),
                          "+f"(acc[mt][nt][2]), "+f"(acc[mt][nt][3])
                        : "r"(aF[mt][0]), "r"(aF[mt][1]), "r"(aF[mt][2]), "r"(aF[mt][3]),
                          "r"(bF[nt][0]), "r"(bF[nt][1]));
        }
        __syncthreads();   // STS(s^1) complete; MMA(s) done -> s reusable next iter
    }

#pragma unroll
    for (int mt = 0; mt < 4; mt++) {
        int row0 = m0 + wm + mt * 16 + g;
        int row1 = row0 + 8;
        float mask0 = 1.0f, mask1 = 1.0f;
        if (rowcnt) {
            if (row0 % rpb >= rowcnt[row0 / rpb]) mask0 = 0.0f;
            if (row1 % rpb >= rowcnt[row1 / rpb]) mask1 = 0.0f;
        }
        float* c0p = C + (size_t)row0 * ldc;
        float* c1p = C + (size_t)row1 * ldc;
#pragma unroll
        for (int nt = 0; nt < 4; nt++) {
            int col = n0 + wn + nt * 8 + 2 * t4;
            float v0 = acc[mt][nt][0], v1 = acc[mt][nt][1];
            float v2 = acc[mt][nt][2], v3 = acc[mt][nt][3];
            if (relu) {
                v0 = fmaxf(v0, 0.f); v1 = fmaxf(v1, 0.f);
                v2 = fmaxf(v2, 0.f); v3 = fmaxf(v3, 0.f);
            }
            float2 w0 = make_float2(v0 * mask0, v1 * mask0);
            float2 w1 = make_float2(v2 * mask1, v3 * mask1);
            *(float2*)(c0p + col) = w0;
            *(float2*)(c1p + col) = w1;
        }
    }
}

// ---- batch A: XWc (32, K=512, cat2) | EgWe (128) | Q (64) ------------------
__global__ __launch_bounds__(256)
void gemm_batchA(const float* __restrict__ NF,
                 const float* __restrict__ Wn, const float* __restrict__ Wn2,
                 const float* __restrict__ We, const float* __restrict__ We2,
                 const int* __restrict__ NOBJ)
{
    extern __shared__ Stage st[];
    int bid = blockIdx.x;
    if (bid < 32) {
        gemm_tile<2>(st, NF, Wn, Wn2, nullptr, d_XWc, DN_, 256, 256, 0,
                     NOBJ, N_, bid & 1, bid >> 1);
    } else if (bid < 160) {
        gemm_tile<1>(st, d_Eg, We, nullptr, nullptr, d_EgWe, DE_, WE_, WE_, 0,
                     nullptr, 0, 0, bid - 32);
    } else {
        gemm_tile<1>(st, d_EFp, We2, nullptr, nullptr, d_pf + 128, DE_, WE_, 256, 1,
                     nullptr, 0, 0, bid - 160);
    }
}

// ---- batch B: hidB (384, cat3 rows 256:512) | nodeY (96, cat3 rows 0:256) --
__global__ __launch_bounds__(256)
void gemm_batchB(const float* __restrict__ lrW1, const float* __restrict__ scrW1,
                 const float* __restrict__ mrW1)
{
    extern __shared__ Stage st[];
    int bid = blockIdx.x;
    if (bid < 384) {
        gemm_tile<3>(st, d_pf, lrW1 + 256 * 256, scrW1 + 256 * 256, mrW1 + 256 * 256,
                     d_hidB, 256, 768, 768, 0, nullptr, 0, bid % 6, bid / 6);
    } else {
        int t = bid - 384;
        gemm_tile<3>(st, d_nemb, lrW1, scrW1, mrW1,
                     d_nodeY, 256, 768, 768, 0, nullptr, 0, t % 6, t / 6);
    }
}

// ------- merged gathers: eg (16384 blocks) | efp (8192 blocks), 64 thr ------
__global__ void gathers(const float* __restrict__ EF, const int* __restrict__ eidx,
                        const int* __restrict__ pairs, const int* __restrict__ nedg)
{
    int bid = blockIdx.x;
    if (bid < B_ * M_) {
        int b = bid / M_, m = bid % M_;
        int s = eidx[(b * 2 + 0) * M_ + m];
        int d = eidx[(b * 2 + 1) * M_ + m];
        bool on = m < nedg[b];
        const float4* src = (const float4*)(EF + (((size_t)b * N_ + s) * N_ + d) * DE_);
        float4* dst = (float4*)(d_Eg + ((size_t)b * M_ + m) * DE_);
        float4 z = make_float4(0.f, 0.f, 0.f, 0.f);
        for (int t = threadIdx.x; t < DE_ / 4; t += blockDim.x)
            dst[t] = on ? src[t] : z;
    } else {
        int t2 = bid - B_ * M_;
        int b = t2 / P_, p = t2 % P_;
        int p0 = pairs[((size_t)b * P_ + p) * 2 + 0];
        int p1 = pairs[((size_t)b * P_ + p) * 2 + 1];
        const float4* src = (const float4*)(EF + (((size_t)b * N_ + p0) * N_ + p1) * DE_);
        float4* dst = (float4*)(d_EFp + ((size_t)b * P_ + p) * DE_);
        for (int t = threadIdx.x; t < DE_ / 4; t += blockDim.x)
            dst[t] = src[t];
    }
}

// ------ stage 3 merged: g (16384 first) | h (2048) | pm (8192), 128 thr -----
// g/h accumulate: 4 warps split the nnz list stride-4; each lane owns a
// float4 column group (32 lanes x 16B = full 128-col row per LDG.128);
// fixed-order cross-warp reduction keeps determinism.
__global__ __launch_bounds__(128)
void stage3(const float* __restrict__ ADJ, const float* __restrict__ LADJ,
            const int* __restrict__ PAIRS, const int* __restrict__ NOBJ,
            const int* __restrict__ NEDG)
{
    __shared__ float s_val[M_];
    __shared__ int   s_idx[M_];
    __shared__ float s_red[4][128];
    __shared__ int   wsum[4];
    int bid = blockIdx.x;
    int w = threadIdx.x;                    // 128
    int lane = w & 31, wp = w >> 5;

    if (bid < B_ * M_) {
        // ---- g = relu(EgWe_m + sum_k L_mk*EgWe_k)*emask (sparse L) ----------
        int b = bid / M_, m = bid % M_;
        const float* Lrow = LADJ + ((size_t)b * M_ + m) * M_;
        float4 va = ((const float4*)Lrow)[w * 2];
        float4 vb = ((const float4*)Lrow)[w * 2 + 1];
        float v[8] = {va.x, va.y, va.z, va.w, vb.x, vb.y, vb.z, vb.w};
        int cnt = 0;
#pragma unroll
        for (int t = 0; t < 8; t++)
            if (v[t] != 0.0f) cnt++;
        int inc = cnt;
#pragma unroll
        for (int d = 1; d < 32; d <<= 1) {
            int t = __shfl_up_sync(0xffffffffu, inc, d);
            if (lane >= d) inc += t;
        }
        if (lane == 31) wsum[wp] = inc;
        __syncthreads();
        int woff = 0;
#pragma unroll
        for (int ww = 0; ww < 4; ww++)
            if (ww < wp) woff += wsum[ww];
        int pos = woff + inc - cnt;         // exclusive prefix
        int base = w * 8;
#pragma unroll
        for (int t = 0; t < 8; t++)
            if (v[t] != 0.0f) { s_idx[pos] = base + t; s_val[pos] = v[t]; pos++; }
        int total = wsum[0] + wsum[1] + wsum[2] + wsum[3];
        __syncthreads();

        const float* Eb = d_EgWe + (size_t)b * M_ * WE_;
        float4 a0 = make_float4(0.f, 0.f, 0.f, 0.f), a1 = a0;
        if (wp == 0)
            a0 = ((const float4*)(Eb + (size_t)m * WE_))[lane];   // identity
        int p = wp;
        for (; p + 4 < total; p += 8) {
            float sv0 = s_val[p];     const float4 e0 = ((const float4*)(Eb + (size_t)s_idx[p]     * WE_))[lane];
            float sv1 = s_val[p + 4]; const float4 e1 = ((const float4*)(Eb + (size_t)s_idx[p + 4] * WE_))[lane];
            a0.x += sv0 * e0.x; a0.y += sv0 * e0.y; a0.z += sv0 * e0.z; a0.w += sv0 * e0.w;
            a1.x += sv1 * e1.x; a1.y += sv1 * e1.y; a1.z += sv1 * e1.z; a1.w += sv1 * e1.w;
        }
        if (p < total) {
            float sv = s_val[p]; const float4 e = ((const float4*)(Eb + (size_t)s_idx[p] * WE_))[lane];
            a0.x += sv * e.x; a0.y += sv * e.y; a0.z += sv * e.z; a0.w += sv * e.w;
        }
        a0.x += a1.x; a0.y += a1.y; a0.z += a1.z; a0.w += a1.w;
        ((float4*)&s_red[wp][0])[lane] = a0;
        __syncthreads();
        float acc = s_red[0][w] + s_red[1][w] + s_red[2][w] + s_red[3][w];
        d_g[((size_t)b * M_ + m) * WE_ + w] =
            (m < NEDG[b]) ? fmaxf(acc, 0.0f) : 0.0f;
    } else if (bid < B_ * M_ + B_ * N_) {
        // ---- h: relu(XW_i + sum_j adj_ij*XW_j)*mask -> nemb cols [0:128) ----
        int t = bid - B_ * M_;
        int b = t / N_, i = t % N_;
        float v = ADJ[((size_t)b * N_ + i) * N_ + w];
        bool nz = v != 0.0f;
        unsigned mk = __ballot_sync(0xffffffffu, nz);
        int rank = __popc(mk & ((1u << lane) - 1));
        if (lane == 0) wsum[wp] = __popc(mk);
        __syncthreads();
        int off = 0;
#pragma unroll
        for (int ww = 0; ww < 4; ww++)
            if (ww < wp) off += wsum[ww];
        if (nz) { s_idx[off + rank] = w; s_val[off + rank] = v; }
        int total = wsum[0] + wsum[1] + wsum[2] + wsum[3];
        __syncthreads();

        const float* XWb = d_XWc + (size_t)b * N_ * 256;   // cols [0:128)
        float4 a0 = make_float4(0.f, 0.f, 0.f, 0.f), a1 = a0;
        if (wp == 0)
            a0 = ((const float4*)(XWb + (size_t)i * 256))[lane];  // identity
        int p = wp;
        for (; p + 4 < total; p += 8) {
            float sv0 = s_val[p];     const float4 e0 = ((const float4*)(XWb + (size_t)s_idx[p]     * 256))[lane];
            float sv1 = s_val[p + 4]; const float4 e1 = ((const float4*)(XWb + (size_t)s_idx[p + 4] * 256))[lane];
            a0.x += sv0 * e0.x; a0.y += sv0 * e0.y; a0.z += sv0 * e0.z; a0.w += sv0 * e0.w;
            a1.x += sv1 * e1.x; a1.y += sv1 * e1.y; a1.z += sv1 * e1.z; a1.w += sv1 * e1.w;
        }
        if (p < total) {
            float sv = s_val[p]; const float4 e = ((const float4*)(XWb + (size_t)s_idx[p] * 256))[lane];
            a0.x += sv * e.x; a0.y += sv * e.y; a0.z += sv * e.z; a0.w += sv * e.w;
        }
        a0.x += a1.x; a0.y += a1.y; a0.z += a1.z; a0.w += a1.w;
        ((float4*)&s_red[wp][0])[lane] = a0;
        __syncthreads();
        float acc = s_red[0][w] + s_red[1][w] + s_red[2][w] + s_red[3][w];
        d_nemb[((size_t)b * N_ + i) * 256 + w] =
            (i < NOBJ[b]) ? fmaxf(acc, 0.0f) : 0.0f;
    } else {
        // ---- Pm = relu(XW2[p0]+XW2[p1]) -> pf cols [0:128) ------------------
        int t = bid - B_ * M_ - B_ * N_;
        int b = t / P_, p = t % P_;
        int p0 = PAIRS[((size_t)b * P_ + p) * 2 + 0];
        int p1 = PAIRS[((size_t)b * P_ + p) * 2 + 1];
        const float* xb = d_XWc + (size_t)b * N_ * 256 + 128;   // cols [128:256)
        d_pf[((size_t)b * P_ + p) * 256 + w] =
            fmaxf(xb[(size_t)p0 * 256 + w] + xb[(size_t)p1 * 256 + w], 0.0f);
    }
}

// ---------------- CSR build: bucket edges by src, stable in m ---------------
__global__ __launch_bounds__(1024)
void csr_kernel(const int* __restrict__ eidx,
                int* __restrict__ order, int* __restrict__ start)
{
    int b = blockIdx.x, m = threadIdx.x;    // 1024 threads
    int warp = m >> 5, lane = m & 31;
    __shared__ int ssrc[M_];
    __shared__ int wcnt[32][N_];            // per-warp histogram
    __shared__ int cnt[N_ + 1];
    ssrc[m] = eidx[(b * 2 + 0) * M_ + m];
    for (int i = m; i < 32 * N_; i += 1024) (&wcnt[0][0])[i] = 0;
    __syncthreads();
    int s = ssrc[m];
    unsigned mk = __match_any_sync(0xffffffffu, s);
    int rank_w = __popc(mk & ((1u << lane) - 1));
    if (lane == (__ffs(mk) - 1)) wcnt[warp][s] = __popc(mk);
    __syncthreads();
    int rank = rank_w;
    for (int ww = 0; ww < warp; ww++) rank += wcnt[ww][s];
    if (m < N_) {
        int t = 0;
        for (int ww = 0; ww < 32; ww++) t += wcnt[ww][m];
        cnt[m + 1] = t;
    }
    if (m == 0) cnt[0] = 0;
    __syncthreads();
    if (m == 0)
        for (int i = 1; i <= N_; i++) cnt[i] += cnt[i - 1];
    __syncthreads();
    order[b * M_ + cnt[s] + rank] = m;
    if (m < N_ + 1) start[b * (N_ + 1) + m] = cnt[m];
}

// -------- agg[b,n] = sum_{m in bucket n, ascending m} g[b,m] * nmask --------
__global__ void agg2_kernel(const int* __restrict__ nobj)
{
    int b = blockIdx.x / N_, n = blockIdx.x % N_;
    int w = threadIdx.x;                    // 128
    int s0 = d_st[b * (N_ + 1) + n], s1 = d_st[b * (N_ + 1) + n + 1];
    const float* gb = d_g + (size_t)b * M_ * WE_;
    const int* ob = d_ord + b * M_;
    float acc = 0.0f;
    for (int i = s0; i < s1; i++)
        acc += gb[(size_t)ob[i] * WE_ + w];
    d_nemb[((size_t)b * N_ + n) * 256 + 128 + w] = (n < nobj[b]) ? acc : 0.0f;
}

// ------ layer-2 heads: hid = relu(hidB + nY[p0] + nY[p1] + b1) fused --------
__global__ void head2_kernel(const int* __restrict__ pairs,
                             const float* __restrict__ lrb1,
                             const float* __restrict__ scrb1,
                             const float* __restrict__ mrb1,
                             const float* __restrict__ lrW2, const float* __restrict__ lrb2,
                             const float* __restrict__ crW2, const float* __restrict__ crb2,
                             const float* __restrict__ mrW2, const float* __restrict__ mrb2,
                             float* __restrict__ out)
{
    __shared__ float sh[8 * 768];
    __shared__ int sp[16];
    int tid = threadIdx.x;                  // 256
    int blk = blockIdx.x;                   // 8 pairs per block
    if (tid < 16) sp[tid] = pairs[(size_t)blk * 16 + tid];
    __syncthreads();
    int b = (blk * 8) / P_;                 // all 8 pairs share batch (P_%8==0)
    const float* nYb = d_nodeY + (size_t)b * N_ * 768;
    for (int i = tid; i < 8 * 768; i += 256) {
        int lp = i / 768, col = i - lp * 768;
        int gg = blk * 8 + lp;
        float b1 = (col < 256) ? lrb1[col]
                 : (col < 512) ? scrb1[col - 256] : mrb1[col - 512];
        float v = d_hidB[(size_t)gg * 768 + col]
                + nYb[(size_t)sp[lp * 2 + 0] * 768 + col]
                + nYb[(size_t)sp[lp * 2 + 1] * 768 + col] + b1;
        sh[i] = fmaxf(v, 0.0f);
    }
    __syncthreads();
    int lp = tid / 32, j = tid % 32;
    int pr = blk * 8 + lp;
    const float* W2; float bias; int nout, oj; const float* hr; size_t obase;
    if (j < 9)       { W2 = lrW2; oj = j;      bias = lrb2[oj]; nout = 9;  hr = sh + lp * 768;       obase = 0; }
    else if (j < 15) { W2 = crW2; oj = j - 9;  bias = crb2[oj]; nout = 6;  hr = sh + lp * 768 + 256; obase = (size_t)B_ * P_ * 9; }
    else             { W2 = mrW2; oj = j - 15; bias = mrb2[oj]; nout = 17; hr = sh + lp * 768 + 512; obase = (size_t)B_ * P_ * 15; }
    float acc = bias;
#pragma unroll 8
    for (int k = 0; k < 256; k++)
        acc += hr[k] * W2[k * nout + oj];
    out[obase + (size_t)pr * nout + oj] = acc;
}

// ============================================================================
extern "C" void kernel_launch(void* const* d_in, const int* in_sizes, int n_in,
                              void* d_out, int out_size)
{
    const float* NF    = (const float*)d_in[0];
    const float* EF    = (const float*)d_in[1];
    const float* ADJ   = (const float*)d_in[2];
    const float* LADJ  = (const float*)d_in[3];
    const int*   EIDX  = (const int*)  d_in[4];
    const int*   PAIRS = (const int*)  d_in[5];
    const int*   NOBJ  = (const int*)  d_in[6];
    const int*   NEDG  = (const int*)  d_in[7];
    const float* Wn    = (const float*)d_in[8];
    const float* We    = (const float*)d_in[9];
    const float* Wn2   = (const float*)d_in[10];
    const float* We2   = (const float*)d_in[11];
    const float* scrW1 = (const float*)d_in[12];
    const float* scrb1 = (const float*)d_in[13];
    const float* scrW2 = (const float*)d_in[14];
    const float* scrb2 = (const float*)d_in[15];
    const float* lrW1  = (const float*)d_in[16];
    const float* lrb1  = (const float*)d_in[17];
    const float* lrW2  = (const float*)d_in[18];
    const float* lrb2  = (const float*)d_in[19];
    const float* mrW1  = (const float*)d_in[20];
    const float* mrb1  = (const float*)d_in[21];
    const float* mrW2  = (const float*)d_in[22];
    const float* mrb2  = (const float*)d_in[23];
    float* out = (float*)d_out;

    int *ord, *st;
    cudaGetSymbolAddress((void**)&ord, d_ord);
    cudaGetSymbolAddress((void**)&st,  d_st);

    const int smemBytes = 2 * (int)sizeof(Stage);   // 69632
    cudaFuncSetAttribute(gemm_batchA, cudaFuncAttributeMaxDynamicSharedMemorySize, smemBytes);
    cudaFuncSetAttribute(gemm_batchB, cudaFuncAttributeMaxDynamicSharedMemorySize, smemBytes);

    // stage 1: CSR + merged gathers (independent)
    csr_kernel<<<B_, 1024>>>(EIDX, ord, st);
    gathers<<<B_ * M_ + B_ * P_, 64>>>(EF, EIDX, PAIRS, NEDG);

    // stage 2: batched GEMM A — XWc(32,K=512,cat2) | EgWe(128) | Q(64)
    gemm_batchA<<<224, 256, smemBytes>>>(NF, Wn, Wn2, We, We2, NOBJ);

    // stage 3: merged g | h | pm (g's long blocks first), then scatter-add
    stage3<<<B_ * M_ + B_ * N_ + B_ * P_, 128>>>(ADJ, LADJ, PAIRS, NOBJ, NEDG);
    agg2_kernel<<<B_ * N_, 128>>>(NOBJ);

    // stage 4: batched GEMM B — hidB(384,cat3) | nodeY(96,cat3)
    gemm_batchB<<<480, 256, smemBytes>>>(lrW1, scrW1, mrW1);

    // stage 5: fused relu-sum (+b1) + layer-2 heads -> out
    head2_kernel<<<B_ * P_ / 8, 256>>>(PAIRS, lrb1, scrb1, mrb1,
                                       lrW2, lrb2, scrW2, scrb2, mrW2, mrb2, out);
}